// round 4
// baseline (speedup 1.0000x reference)
#include <cuda_runtime.h>
#include <math.h>
#include <stdint.h>

// Problem constants (hardcoded per reference: B=2, H=W=256, C=256, NH=8, WS=8, SHIFT=4)
#define MTOK   131072          // B * H * W tokens
#define CD     256
#define NWIN   2048            // B * (H/8)*(W/8)
#define HIDDEN 1024

// ---------------- static scratch (no runtime allocation allowed) ----------------
__device__ float g_h  [(size_t)MTOK * CD];      // LN1 output, window-partitioned order
__device__ float g_q  [(size_t)MTOK * CD];
__device__ float g_k  [(size_t)MTOK * CD];
__device__ float g_v  [(size_t)MTOK * CD];
__device__ float g_att[(size_t)MTOK * CD];      // attn output, [bw][head][n][d]
__device__ float g_y2 [(size_t)MTOK * CD];      // LN2 output (second-residual source)
__device__ float g_u  [(size_t)MTOK * HIDDEN];  // fc1+gelu output

// ---------------- block-wide (256-thread) dual reduction ----------------
__device__ __forceinline__ void blockReduce2(float& a, float& b) {
    __shared__ float sa[8], sb[8];
    int lane = threadIdx.x & 31, wid = threadIdx.x >> 5;
#pragma unroll
    for (int o = 16; o; o >>= 1) {
        a += __shfl_xor_sync(0xffffffffu, a, o);
        b += __shfl_xor_sync(0xffffffffu, b, o);
    }
    if (lane == 0) { sa[wid] = a; sb[wid] = b; }
    __syncthreads();
    a = 0.f; b = 0.f;
#pragma unroll
    for (int i = 0; i < 8; i++) { a += sa[i]; b += sb[i]; }
}

// ---------------- kernel 1: LN1 fused with shift-roll + window partition ----------------
// Output row m (window order): bw = m/64, n = m%64. Gathers rolled source token.
__global__ void ln1_window_kernel(const float* __restrict__ x,
                                  const float* __restrict__ g1,
                                  const float* __restrict__ b1,
                                  float* __restrict__ h) {
    int m = blockIdx.x;
    int tid = threadIdx.x;                 // 256 threads = channels
    int bw = m >> 6, n = m & 63;
    int bb = bw >> 10, widx = bw & 1023;
    int wh = widx >> 5, ww = widx & 31;
    int r = n >> 3, c = n & 7;
    int gh = (wh * 8 + r + 4) & 255;       // roll(x, -4)
    int gw = (ww * 8 + c + 4) & 255;
    const float* row = x + ((size_t)bb * 65536 + (size_t)gh * 256 + gw) * CD;
    float v = row[tid];
    float a = v, b = v * v;
    blockReduce2(a, b);
    float mu = a * (1.0f / CD);
    float var = b * (1.0f / CD) - mu * mu;
    float rstd = rsqrtf(var + 1e-5f);
    h[(size_t)m * CD + tid] = (v - mu) * rstd * g1[tid] + b1[tid];
}

// ---------------- kernel 2: generic SGEMM, BM=BN=128, BK=8, 8x8 microtiles ----------------
// C[M,Nn] = A[M,K] @ B[K,Nn] + bias (+ optional exact GELU, + optional residual)
template <bool GELU, bool RES>
__global__ void sgemm128(const float* __restrict__ A, const float* __restrict__ B,
                         const float* __restrict__ bias, const float* __restrict__ res,
                         float* __restrict__ C, int M, int Nn, int K) {
    __shared__ float As[8][128];
    __shared__ float Bs[8][128];
    int tid = threadIdx.x;                 // 256 threads
    int tx = tid & 15, ty = tid >> 4;
    int m0 = blockIdx.y * 128;
    int n0 = blockIdx.x * 128;

    int arow = tid >> 1, acol = (tid & 1) << 2;     // A tile: 128x8
    int brow = tid >> 5, bcol = (tid & 31) << 2;    // B tile: 8x128

    const float* Aptr = A + (size_t)(m0 + arow) * K + acol;
    const float* Bptr = B + (size_t)brow * Nn + n0 + bcol;

    float acc[8][8] = {};
    float4 av = *(const float4*)(Aptr);
    float4 bv = *(const float4*)(Bptr);

    for (int k0 = 0; k0 < K; k0 += 8) {
        As[acol + 0][arow] = av.x;
        As[acol + 1][arow] = av.y;
        As[acol + 2][arow] = av.z;
        As[acol + 3][arow] = av.w;
        *(float4*)&Bs[brow][bcol] = bv;
        __syncthreads();
        if (k0 + 8 < K) {
            av = *(const float4*)(Aptr + k0 + 8);
            bv = *(const float4*)(Bptr + (size_t)(k0 + 8) * Nn);
        }
#pragma unroll
        for (int kk = 0; kk < 8; kk++) {
            float a[8], b[8];
            *(float4*)&a[0] = *(const float4*)&As[kk][ty * 4];
            *(float4*)&a[4] = *(const float4*)&As[kk][64 + ty * 4];
            *(float4*)&b[0] = *(const float4*)&Bs[kk][tx * 4];
            *(float4*)&b[4] = *(const float4*)&Bs[kk][64 + tx * 4];
#pragma unroll
            for (int i = 0; i < 8; i++)
#pragma unroll
                for (int j = 0; j < 8; j++) acc[i][j] += a[i] * b[j];
        }
        __syncthreads();
    }

#pragma unroll
    for (int i = 0; i < 8; i++) {
        int row = m0 + ((i < 4) ? (ty * 4 + i) : (64 + ty * 4 + i - 4));
#pragma unroll
        for (int half = 0; half < 2; half++) {
            int col = n0 + half * 64 + tx * 4;
            float4 bia = *(const float4*)(bias + col);
            float4 o;
            o.x = acc[i][half * 4 + 0] + bia.x;
            o.y = acc[i][half * 4 + 1] + bia.y;
            o.z = acc[i][half * 4 + 2] + bia.z;
            o.w = acc[i][half * 4 + 3] + bia.w;
            if (GELU) {
                o.x = 0.5f * o.x * (1.0f + erff(o.x * 0.70710678118654752f));
                o.y = 0.5f * o.y * (1.0f + erff(o.y * 0.70710678118654752f));
                o.z = 0.5f * o.z * (1.0f + erff(o.z * 0.70710678118654752f));
                o.w = 0.5f * o.w * (1.0f + erff(o.w * 0.70710678118654752f));
            }
            if (RES) {
                float4 rr = *(const float4*)(res + (size_t)row * Nn + col);
                o.x += rr.x; o.y += rr.y; o.z += rr.z; o.w += rr.w;
            }
            *(float4*)&C[(size_t)row * Nn + col] = o;
        }
    }
}

// ---------------- kernel 3: windowed attention, one block per (window, head) ----------------
__global__ void attn_kernel(const float* __restrict__ q, const float* __restrict__ k,
                            const float* __restrict__ v,
                            const float* __restrict__ bias_table,
                            float* __restrict__ attn_out) {
    int blk = blockIdx.x;               // bw*8 + head
    int bw = blk >> 3, head = blk & 7;
    int widx = bw & 1023;
    int wh = widx >> 5, ww = widx & 31;
    int tid = threadIdx.x;              // 256 threads

    __shared__ float sq[64][33];
    __shared__ float sk[64][33];
    __shared__ float sv[64][36];        // stride multiple of 4 for float4 reads
    __shared__ float sc[64][65];
    __shared__ int   lab[64];

    // load q,k,v head-slices: 64x32 each; thread -> (n = tid/4, d0 = (tid%4)*8)
    {
        int n = tid >> 2, d0 = (tid & 3) << 3;
        size_t off = ((size_t)bw * 64 + n) * CD + head * 32 + d0;
        float4 a0 = *(const float4*)(q + off);
        float4 a1 = *(const float4*)(q + off + 4);
        sq[n][d0 + 0] = a0.x; sq[n][d0 + 1] = a0.y; sq[n][d0 + 2] = a0.z; sq[n][d0 + 3] = a0.w;
        sq[n][d0 + 4] = a1.x; sq[n][d0 + 5] = a1.y; sq[n][d0 + 6] = a1.z; sq[n][d0 + 7] = a1.w;
        float4 c0 = *(const float4*)(k + off);
        float4 c1 = *(const float4*)(k + off + 4);
        sk[n][d0 + 0] = c0.x; sk[n][d0 + 1] = c0.y; sk[n][d0 + 2] = c0.z; sk[n][d0 + 3] = c0.w;
        sk[n][d0 + 4] = c1.x; sk[n][d0 + 5] = c1.y; sk[n][d0 + 6] = c1.z; sk[n][d0 + 7] = c1.w;
        float4 v0 = *(const float4*)(v + off);
        float4 v1 = *(const float4*)(v + off + 4);
        *(float4*)&sv[n][d0]     = v0;
        *(float4*)&sv[n][d0 + 4] = v1;
    }
    // region labels for shift mask
    if (tid < 64) {
        int ri = tid >> 3, ci = tid & 7;
        int srow = wh * 8 + ri, scol = ww * 8 + ci;
        int lh = (srow < 248) ? 0 : ((srow < 252) ? 1 : 2);
        int lw = (scol < 248) ? 0 : ((scol < 252) ? 1 : 2);
        lab[tid] = lh * 3 + lw;
    }
    __syncthreads();

    // scores: 16x16 thread grid, each computes a 4x4 tile of the 64x64 score matrix
    {
        int i0 = (tid >> 4) << 2, j0 = (tid & 15) << 2;
        float accs[4][4] = {};
#pragma unroll 8
        for (int d = 0; d < 32; d++) {
            float a0 = sq[i0 + 0][d], a1 = sq[i0 + 1][d], a2 = sq[i0 + 2][d], a3 = sq[i0 + 3][d];
            float b0 = sk[j0 + 0][d], b1 = sk[j0 + 1][d], b2 = sk[j0 + 2][d], b3 = sk[j0 + 3][d];
            accs[0][0] += a0 * b0; accs[0][1] += a0 * b1; accs[0][2] += a0 * b2; accs[0][3] += a0 * b3;
            accs[1][0] += a1 * b0; accs[1][1] += a1 * b1; accs[1][2] += a1 * b2; accs[1][3] += a1 * b3;
            accs[2][0] += a2 * b0; accs[2][1] += a2 * b1; accs[2][2] += a2 * b2; accs[2][3] += a2 * b3;
            accs[3][0] += a3 * b0; accs[3][1] += a3 * b1; accs[3][2] += a3 * b2; accs[3][3] += a3 * b3;
        }
        const float sscale = 0.17677669529663687f;  // 1/sqrt(32)
#pragma unroll
        for (int ii = 0; ii < 4; ii++) {
            int i = i0 + ii;
            int ri = i >> 3, ci = i & 7, li = lab[i];
#pragma unroll
            for (int jj = 0; jj < 4; jj++) {
                int j = j0 + jj;
                int rj = j >> 3, cj = j & 7;
                int rel = (ri - rj + 7) * 15 + (ci - cj + 7);
                float s = accs[ii][jj] * sscale + bias_table[rel * 8 + head];
                if (li != lab[j]) s -= 100.0f;
                sc[i][j] = s;
            }
        }
    }
    __syncthreads();

    // softmax: 4 threads per row (sub-group shuffles)
    {
        int row = tid >> 2, sub = tid & 3;
        float mx = -1e30f;
#pragma unroll
        for (int t = 0; t < 16; t++) mx = fmaxf(mx, sc[row][sub * 16 + t]);
        mx = fmaxf(mx, __shfl_xor_sync(0xffffffffu, mx, 1));
        mx = fmaxf(mx, __shfl_xor_sync(0xffffffffu, mx, 2));
        float sum = 0.f;
#pragma unroll
        for (int t = 0; t < 16; t++) {
            float e = __expf(sc[row][sub * 16 + t] - mx);
            sc[row][sub * 16 + t] = e;
            sum += e;
        }
        sum += __shfl_xor_sync(0xffffffffu, sum, 1);
        sum += __shfl_xor_sync(0xffffffffu, sum, 2);
        float inv = 1.0f / sum;
#pragma unroll
        for (int t = 0; t < 16; t++) sc[row][sub * 16 + t] *= inv;
    }
    __syncthreads();

    // out = attn @ v : thread -> (i = tid/4, d0 = (tid%4)*8)
    {
        int i = tid >> 2, d0 = (tid & 3) << 3;
        float acc[8] = {};
#pragma unroll 16
        for (int j = 0; j < 64; j++) {
            float s = sc[i][j];
            float4 v0 = *(const float4*)&sv[j][d0];
            float4 v1 = *(const float4*)&sv[j][d0 + 4];
            acc[0] += s * v0.x; acc[1] += s * v0.y; acc[2] += s * v0.z; acc[3] += s * v0.w;
            acc[4] += s * v1.x; acc[5] += s * v1.y; acc[6] += s * v1.z; acc[7] += s * v1.w;
        }
        size_t o = (((size_t)bw * 8 + head) * 64 + i) * 32 + d0;
        float4 o0 = {acc[0], acc[1], acc[2], acc[3]};
        float4 o1 = {acc[4], acc[5], acc[6], acc[7]};
        *(float4*)&attn_out[o]     = o0;
        *(float4*)&attn_out[o + 4] = o1;
    }
}

// ---------------- kernel 4: un-window + un-roll + residual + LN2 ----------------
// Channel assembly is contiguous because head==r in the reference's head-less reshape.
__global__ void unwin_res_ln2(const float* __restrict__ x, const float* __restrict__ att,
                              const float* __restrict__ g2, const float* __restrict__ b2,
                              float* __restrict__ y2) {
    int m = blockIdx.x;
    int ch = threadIdx.x;
    int bb = m >> 16, l = m & 65535;
    int gh = l >> 8, gw = l & 255;
    int sh = (gh + 252) & 255, sw = (gw + 252) & 255;   // roll(+4) inverse
    int wh = sh >> 3, r = sh & 7, ww = sw >> 3, c = sw & 7;
    size_t base = ((size_t)((bb * 1024 + wh * 32 + ww) * 8 + r) * 64 + (size_t)c * 8) * 32;
    float v = x[(size_t)m * CD + ch] + att[base + ch];
    float a = v, b = v * v;
    blockReduce2(a, b);
    float mu = a * (1.0f / CD);
    float var = b * (1.0f / CD) - mu * mu;
    float rstd = rsqrtf(var + 1e-5f);
    y2[(size_t)m * CD + ch] = (v - mu) * rstd * g2[ch] + b2[ch];
}

// ---------------- host launch ----------------
extern "C" void kernel_launch(void* const* d_in, const int* in_sizes, int n_in,
                              void* d_out, int out_size) {
    (void)in_sizes; (void)n_in; (void)out_size;
    const float* x    = (const float*)d_in[0];
    const float* g1   = (const float*)d_in[1];
    const float* b1   = (const float*)d_in[2];
    const float* wq   = (const float*)d_in[3];
    const float* bq   = (const float*)d_in[4];
    const float* wk   = (const float*)d_in[5];
    const float* bk   = (const float*)d_in[6];
    const float* wv   = (const float*)d_in[7];
    const float* bv   = (const float*)d_in[8];
    const float* tbl  = (const float*)d_in[9];
    const float* g2   = (const float*)d_in[10];
    const float* b2   = (const float*)d_in[11];
    const float* wf1  = (const float*)d_in[12];
    const float* bf1  = (const float*)d_in[13];
    const float* wf2  = (const float*)d_in[14];
    const float* bf2  = (const float*)d_in[15];
    float* out = (float*)d_out;

    float *p_h, *p_q, *p_k, *p_v, *p_att, *p_y2, *p_u;
    cudaGetSymbolAddress((void**)&p_h,   g_h);
    cudaGetSymbolAddress((void**)&p_q,   g_q);
    cudaGetSymbolAddress((void**)&p_k,   g_k);
    cudaGetSymbolAddress((void**)&p_v,   g_v);
    cudaGetSymbolAddress((void**)&p_att, g_att);
    cudaGetSymbolAddress((void**)&p_y2,  g_y2);
    cudaGetSymbolAddress((void**)&p_u,   g_u);

    // 1. LN1 + shift + window partition
    ln1_window_kernel<<<MTOK, 256>>>(x, g1, b1, p_h);

    // 2. Q/K/V projections
    sgemm128<false, false><<<dim3(CD / 128, MTOK / 128), 256>>>(p_h, wq, bq, nullptr, p_q, MTOK, CD, CD);
    sgemm128<false, false><<<dim3(CD / 128, MTOK / 128), 256>>>(p_h, wk, bk, nullptr, p_k, MTOK, CD, CD);
    sgemm128<false, false><<<dim3(CD / 128, MTOK / 128), 256>>>(p_h, wv, bv, nullptr, p_v, MTOK, CD, CD);

    // 3. windowed attention (bias + mask + softmax fused)
    attn_kernel<<<NWIN * 8, 256>>>(p_q, p_k, p_v, tbl, p_att);

    // 4. reverse window/roll + residual + LN2
    unwin_res_ln2<<<MTOK, 256>>>(x, p_att, g2, b2, p_y2);

    // 5. MLP: fc1 + exact GELU, then fc2 + residual (writes final output)
    sgemm128<true,  false><<<dim3(HIDDEN / 128, MTOK / 128), 256>>>(p_y2, wf1, bf1, nullptr, p_u, MTOK, HIDDEN, CD);
    sgemm128<false, true ><<<dim3(CD / 128, MTOK / 128), 256>>>(p_u, wf2, bf2, p_y2, out, MTOK, CD, HIDDEN);
}

// round 6
// speedup vs baseline: 2.0159x; 2.0159x over previous
#include <cuda_runtime.h>
#include <math.h>
#include <stdint.h>

// Problem constants (hardcoded per reference: B=2, H=W=256, C=256, NH=8, WS=8, SHIFT=4)
#define MTOK   131072          // B * H * W tokens
#define CD     256
#define NWIN   2048            // B * (H/8)*(W/8)
#define HIDDEN 1024

// ---------------- static scratch (no runtime allocation allowed) ----------------
__device__ float g_h  [(size_t)MTOK * CD];      // LN1 output, window-partitioned order
__device__ float g_q  [(size_t)MTOK * CD];
__device__ float g_k  [(size_t)MTOK * CD];
__device__ float g_v  [(size_t)MTOK * CD];
__device__ float g_att[(size_t)MTOK * CD];      // attn output, [bw][head][n][d]
__device__ float g_y2 [(size_t)MTOK * CD];      // LN2 output (second-residual source)
__device__ float g_u  [(size_t)MTOK * HIDDEN];  // fc1+gelu output

// ---------------- block-wide (256-thread) dual reduction ----------------
__device__ __forceinline__ void blockReduce2(float& a, float& b) {
    __shared__ float sa[8], sb[8];
    int lane = threadIdx.x & 31, wid = threadIdx.x >> 5;
#pragma unroll
    for (int o = 16; o; o >>= 1) {
        a += __shfl_xor_sync(0xffffffffu, a, o);
        b += __shfl_xor_sync(0xffffffffu, b, o);
    }
    if (lane == 0) { sa[wid] = a; sb[wid] = b; }
    __syncthreads();
    a = 0.f; b = 0.f;
#pragma unroll
    for (int i = 0; i < 8; i++) { a += sa[i]; b += sb[i]; }
}

// ---------------- kernel 1: LN1 fused with shift-roll + window partition ----------------
__global__ void ln1_window_kernel(const float* __restrict__ x,
                                  const float* __restrict__ g1,
                                  const float* __restrict__ b1,
                                  float* __restrict__ h) {
    int m = blockIdx.x;
    int tid = threadIdx.x;                 // 256 threads = channels
    int bw = m >> 6, n = m & 63;
    int bb = bw >> 10, widx = bw & 1023;
    int wh = widx >> 5, ww = widx & 31;
    int r = n >> 3, c = n & 7;
    int gh = (wh * 8 + r + 4) & 255;       // roll(x, -4)
    int gw = (ww * 8 + c + 4) & 255;
    const float* row = x + ((size_t)bb * 65536 + (size_t)gh * 256 + gw) * CD;
    float v = row[tid];
    float a = v, b = v * v;
    blockReduce2(a, b);
    float mu = a * (1.0f / CD);
    float var = b * (1.0f / CD) - mu * mu;
    float rstd = rsqrtf(var + 1e-5f);
    h[(size_t)m * CD + tid] = (v - mu) * rstd * g1[tid] + b1[tid];
}

// ---------------- tf32 tensor-core GEMM ----------------
__device__ __forceinline__ uint32_t f2tf(float f) {
    uint32_t u; asm("cvt.rna.tf32.f32 %0, %1;" : "=r"(u) : "f"(f)); return u;
}
__device__ __forceinline__ void ldsm4(uint32_t& r0, uint32_t& r1, uint32_t& r2, uint32_t& r3,
                                      uint32_t addr) {
    asm volatile("ldmatrix.sync.aligned.m8n8.x4.shared.b16 {%0,%1,%2,%3}, [%4];"
                 : "=r"(r0), "=r"(r1), "=r"(r2), "=r"(r3) : "r"(addr));
}
__device__ __forceinline__ void mma_tf32(float* c, const uint32_t* a, const uint32_t* b) {
    asm volatile(
        "mma.sync.aligned.m16n8k8.row.col.f32.tf32.tf32.f32 "
        "{%0,%1,%2,%3}, {%4,%5,%6,%7}, {%8,%9}, {%0,%1,%2,%3};"
        : "+f"(c[0]), "+f"(c[1]), "+f"(c[2]), "+f"(c[3])
        : "r"(a[0]), "r"(a[1]), "r"(a[2]), "r"(a[3]), "r"(b[0]), "r"(b[1]));
}

// C[M,Nn] = A[M,K] @ B[K,Nn] + bias (+ optional exact GELU, + optional residual)
// BM=BN=128, BK=32; 8 warps (4m x 2n), warp tile 32x64 = 2x8 m16n8k8 frags.
// Smem layout (both operands): [row][32 floats], 16B group index XOR'ed with (row&7).
// A stored m-major [m][k]; B stored TRANSPOSED n-major [n][k] (mma needs B col-major).
template <bool GELU, bool RES>
__global__ void __launch_bounds__(256, 1)
tgemm(const float* __restrict__ A, const float* __restrict__ B,
      const float* __restrict__ bias, const float* __restrict__ res,
      float* __restrict__ C, int M, int Nn, int K) {
    __shared__ __align__(16) uint32_t As[128 * 32];
    __shared__ __align__(16) uint32_t Bs[128 * 32];
    int tid = threadIdx.x;
    int lane = tid & 31, wid = tid >> 5;
    int wm = wid >> 1, wn = wid & 1;
    int m0 = blockIdx.y * 128, n0 = blockIdx.x * 128;

    uint32_t asBase = (uint32_t)__cvta_generic_to_shared(As);
    uint32_t bsBase = (uint32_t)__cvta_generic_to_shared(Bs);

    float acc[2][8][4] = {};

    // prefetch tile 0 into registers
    float4 apre[4];
    float  bpre[4][4];
#pragma unroll
    for (int i = 0; i < 4; i++) {
        int idx = tid + 256 * i;
        int am = idx >> 3, akq = idx & 7;
        apre[i] = *(const float4*)(A + (size_t)(m0 + am) * K + akq * 4);
        int bn = idx & 127, bkq = idx >> 7;
#pragma unroll
        for (int j = 0; j < 4; j++)
            bpre[i][j] = B[(size_t)(bkq * 4 + j) * Nn + n0 + bn];
    }

    for (int k0 = 0; k0 < K; k0 += 32) {
        // store prefetched tile (converted to tf32) into swizzled smem
#pragma unroll
        for (int i = 0; i < 4; i++) {
            int idx = tid + 256 * i;
            int am = idx >> 3, akq = idx & 7;
            uint4 av = { f2tf(apre[i].x), f2tf(apre[i].y), f2tf(apre[i].z), f2tf(apre[i].w) };
            *(uint4*)&As[am * 32 + ((akq ^ (am & 7)) << 2)] = av;
            int bn = idx & 127, bkq = idx >> 7;
            uint4 bv = { f2tf(bpre[i][0]), f2tf(bpre[i][1]), f2tf(bpre[i][2]), f2tf(bpre[i][3]) };
            *(uint4*)&Bs[bn * 32 + ((bkq ^ (bn & 7)) << 2)] = bv;
        }
        __syncthreads();

        // prefetch next tile
        if (k0 + 32 < K) {
#pragma unroll
            for (int i = 0; i < 4; i++) {
                int idx = tid + 256 * i;
                int am = idx >> 3, akq = idx & 7;
                apre[i] = *(const float4*)(A + (size_t)(m0 + am) * K + k0 + 32 + akq * 4);
                int bn = idx & 127, bkq = idx >> 7;
#pragma unroll
                for (int j = 0; j < 4; j++)
                    bpre[i][j] = B[(size_t)(k0 + 32 + bkq * 4 + j) * Nn + n0 + bn];
            }
        }

        int r = lane & 7, quad = lane >> 3;
#pragma unroll
        for (int kk = 0; kk < 4; kk++) {
            uint32_t af[2][4];
#pragma unroll
            for (int mt = 0; mt < 2; mt++) {
                int row = wm * 32 + mt * 16 + ((quad & 1) << 3) + r;
                int grp = ((kk << 1) | (quad >> 1)) ^ (row & 7);
                ldsm4(af[mt][0], af[mt][1], af[mt][2], af[mt][3],
                      asBase + ((row * 32 + grp * 4) << 2));
            }
            uint32_t bf[8][2];
#pragma unroll
            for (int p = 0; p < 4; p++) {
                int nn = wn * 64 + p * 16 + ((quad >> 1) << 3) + r;
                int grp = ((kk << 1) | (quad & 1)) ^ (nn & 7);
                ldsm4(bf[2 * p][0], bf[2 * p][1], bf[2 * p + 1][0], bf[2 * p + 1][1],
                      bsBase + ((nn * 32 + grp * 4) << 2));
            }
#pragma unroll
            for (int mt = 0; mt < 2; mt++)
#pragma unroll
                for (int nt = 0; nt < 8; nt++)
                    mma_tf32(acc[mt][nt], af[mt], bf[nt]);
        }
        __syncthreads();
    }

    // epilogue: d0 (r,c), d1 (r,c+1), d2 (r+8,c), d3 (r+8,c+1); r=lane/4, c=(lane%4)*2
    int r0 = lane >> 2, c0 = (lane & 3) << 1;
#pragma unroll
    for (int mt = 0; mt < 2; mt++) {
#pragma unroll
        for (int half = 0; half < 2; half++) {
            int row = m0 + wm * 32 + mt * 16 + half * 8 + r0;
#pragma unroll
            for (int nt = 0; nt < 8; nt++) {
                int col = n0 + wn * 64 + nt * 8 + c0;
                float v0 = acc[mt][nt][half * 2 + 0] + bias[col];
                float v1 = acc[mt][nt][half * 2 + 1] + bias[col + 1];
                if (GELU) {
                    v0 = 0.5f * v0 * (1.0f + erff(v0 * 0.70710678118654752f));
                    v1 = 0.5f * v1 * (1.0f + erff(v1 * 0.70710678118654752f));
                }
                if (RES) {
                    v0 += res[(size_t)row * Nn + col];
                    v1 += res[(size_t)row * Nn + col + 1];
                }
                *(float2*)&C[(size_t)row * Nn + col] = make_float2(v0, v1);
            }
        }
    }
}

// ---------------- kernel 3: windowed attention, one block per (window, head) ----------------
__global__ void attn_kernel(const float* __restrict__ q, const float* __restrict__ k,
                            const float* __restrict__ v,
                            const float* __restrict__ bias_table,
                            float* __restrict__ attn_out) {
    int blk = blockIdx.x;               // bw*8 + head
    int bw = blk >> 3, head = blk & 7;
    int widx = bw & 1023;
    int wh = widx >> 5, ww = widx & 31;
    int tid = threadIdx.x;              // 256 threads

    __shared__ float sq[64][33];
    __shared__ float sk[64][33];
    __shared__ float sv[64][36];        // stride multiple of 4 for float4 reads
    __shared__ float sc[64][65];
    __shared__ int   lab[64];

    // load q,k,v head-slices: 64x32 each; thread -> (n = tid/4, d0 = (tid%4)*8)
    {
        int n = tid >> 2, d0 = (tid & 3) << 3;
        size_t off = ((size_t)bw * 64 + n) * CD + head * 32 + d0;
        float4 a0 = *(const float4*)(q + off);
        float4 a1 = *(const float4*)(q + off + 4);
        sq[n][d0 + 0] = a0.x; sq[n][d0 + 1] = a0.y; sq[n][d0 + 2] = a0.z; sq[n][d0 + 3] = a0.w;
        sq[n][d0 + 4] = a1.x; sq[n][d0 + 5] = a1.y; sq[n][d0 + 6] = a1.z; sq[n][d0 + 7] = a1.w;
        float4 c0 = *(const float4*)(k + off);
        float4 c1 = *(const float4*)(k + off + 4);
        sk[n][d0 + 0] = c0.x; sk[n][d0 + 1] = c0.y; sk[n][d0 + 2] = c0.z; sk[n][d0 + 3] = c0.w;
        sk[n][d0 + 4] = c1.x; sk[n][d0 + 5] = c1.y; sk[n][d0 + 6] = c1.z; sk[n][d0 + 7] = c1.w;
        float4 v0 = *(const float4*)(v + off);
        float4 v1 = *(const float4*)(v + off + 4);
        *(float4*)&sv[n][d0]     = v0;
        *(float4*)&sv[n][d0 + 4] = v1;
    }
    // region labels for shift mask
    if (tid < 64) {
        int ri = tid >> 3, ci = tid & 7;
        int srow = wh * 8 + ri, scol = ww * 8 + ci;
        int lh = (srow < 248) ? 0 : ((srow < 252) ? 1 : 2);
        int lw = (scol < 248) ? 0 : ((scol < 252) ? 1 : 2);
        lab[tid] = lh * 3 + lw;
    }
    __syncthreads();

    // scores: 16x16 thread grid, each computes a 4x4 tile of the 64x64 score matrix
    {
        int i0 = (tid >> 4) << 2, j0 = (tid & 15) << 2;
        float accs[4][4] = {};
#pragma unroll 8
        for (int d = 0; d < 32; d++) {
            float a0 = sq[i0 + 0][d], a1 = sq[i0 + 1][d], a2 = sq[i0 + 2][d], a3 = sq[i0 + 3][d];
            float b0 = sk[j0 + 0][d], b1 = sk[j0 + 1][d], b2 = sk[j0 + 2][d], b3 = sk[j0 + 3][d];
            accs[0][0] += a0 * b0; accs[0][1] += a0 * b1; accs[0][2] += a0 * b2; accs[0][3] += a0 * b3;
            accs[1][0] += a1 * b0; accs[1][1] += a1 * b1; accs[1][2] += a1 * b2; accs[1][3] += a1 * b3;
            accs[2][0] += a2 * b0; accs[2][1] += a2 * b1; accs[2][2] += a2 * b2; accs[2][3] += a2 * b3;
            accs[3][0] += a3 * b0; accs[3][1] += a3 * b1; accs[3][2] += a3 * b2; accs[3][3] += a3 * b3;
        }
        const float sscale = 0.17677669529663687f;  // 1/sqrt(32)
#pragma unroll
        for (int ii = 0; ii < 4; ii++) {
            int i = i0 + ii;
            int ri = i >> 3, ci = i & 7, li = lab[i];
#pragma unroll
            for (int jj = 0; jj < 4; jj++) {
                int j = j0 + jj;
                int rj = j >> 3, cj = j & 7;
                int rel = (ri - rj + 7) * 15 + (ci - cj + 7);
                float s = accs[ii][jj] * sscale + bias_table[rel * 8 + head];
                if (li != lab[j]) s -= 100.0f;
                sc[i][j] = s;
            }
        }
    }
    __syncthreads();

    // softmax: 4 threads per row (sub-group shuffles)
    {
        int row = tid >> 2, sub = tid & 3;
        float mx = -1e30f;
#pragma unroll
        for (int t = 0; t < 16; t++) mx = fmaxf(mx, sc[row][sub * 16 + t]);
        mx = fmaxf(mx, __shfl_xor_sync(0xffffffffu, mx, 1));
        mx = fmaxf(mx, __shfl_xor_sync(0xffffffffu, mx, 2));
        float sum = 0.f;
#pragma unroll
        for (int t = 0; t < 16; t++) {
            float e = __expf(sc[row][sub * 16 + t] - mx);
            sc[row][sub * 16 + t] = e;
            sum += e;
        }
        sum += __shfl_xor_sync(0xffffffffu, sum, 1);
        sum += __shfl_xor_sync(0xffffffffu, sum, 2);
        float inv = 1.0f / sum;
#pragma unroll
        for (int t = 0; t < 16; t++) sc[row][sub * 16 + t] *= inv;
    }
    __syncthreads();

    // out = attn @ v : thread -> (i = tid/4, d0 = (tid%4)*8)
    {
        int i = tid >> 2, d0 = (tid & 3) << 3;
        float acc[8] = {};
#pragma unroll 16
        for (int j = 0; j < 64; j++) {
            float s = sc[i][j];
            float4 v0 = *(const float4*)&sv[j][d0];
            float4 v1 = *(const float4*)&sv[j][d0 + 4];
            acc[0] += s * v0.x; acc[1] += s * v0.y; acc[2] += s * v0.z; acc[3] += s * v0.w;
            acc[4] += s * v1.x; acc[5] += s * v1.y; acc[6] += s * v1.z; acc[7] += s * v1.w;
        }
        size_t o = (((size_t)bw * 8 + head) * 64 + i) * 32 + d0;
        float4 o0 = {acc[0], acc[1], acc[2], acc[3]};
        float4 o1 = {acc[4], acc[5], acc[6], acc[7]};
        *(float4*)&attn_out[o]     = o0;
        *(float4*)&attn_out[o + 4] = o1;
    }
}

// ---------------- kernel 4: un-window + un-roll + residual + LN2 ----------------
__global__ void unwin_res_ln2(const float* __restrict__ x, const float* __restrict__ att,
                              const float* __restrict__ g2, const float* __restrict__ b2,
                              float* __restrict__ y2) {
    int m = blockIdx.x;
    int ch = threadIdx.x;
    int bb = m >> 16, l = m & 65535;
    int gh = l >> 8, gw = l & 255;
    int sh = (gh + 252) & 255, sw = (gw + 252) & 255;   // roll(+4) inverse
    int wh = sh >> 3, r = sh & 7, ww = sw >> 3, c = sw & 7;
    size_t base = ((size_t)((bb * 1024 + wh * 32 + ww) * 8 + r) * 64 + (size_t)c * 8) * 32;
    float v = x[(size_t)m * CD + ch] + att[base + ch];
    float a = v, b = v * v;
    blockReduce2(a, b);
    float mu = a * (1.0f / CD);
    float var = b * (1.0f / CD) - mu * mu;
    float rstd = rsqrtf(var + 1e-5f);
    y2[(size_t)m * CD + ch] = (v - mu) * rstd * g2[ch] + b2[ch];
}

// ---------------- host launch ----------------
extern "C" void kernel_launch(void* const* d_in, const int* in_sizes, int n_in,
                              void* d_out, int out_size) {
    (void)in_sizes; (void)n_in; (void)out_size;
    const float* x    = (const float*)d_in[0];
    const float* g1   = (const float*)d_in[1];
    const float* b1   = (const float*)d_in[2];
    const float* wq   = (const float*)d_in[3];
    const float* bq   = (const float*)d_in[4];
    const float* wk   = (const float*)d_in[5];
    const float* bk   = (const float*)d_in[6];
    const float* wv   = (const float*)d_in[7];
    const float* bv   = (const float*)d_in[8];
    const float* tbl  = (const float*)d_in[9];
    const float* g2   = (const float*)d_in[10];
    const float* b2   = (const float*)d_in[11];
    const float* wf1  = (const float*)d_in[12];
    const float* bf1  = (const float*)d_in[13];
    const float* wf2  = (const float*)d_in[14];
    const float* bf2  = (const float*)d_in[15];
    float* out = (float*)d_out;

    float *p_h, *p_q, *p_k, *p_v, *p_att, *p_y2, *p_u;
    cudaGetSymbolAddress((void**)&p_h,   g_h);
    cudaGetSymbolAddress((void**)&p_q,   g_q);
    cudaGetSymbolAddress((void**)&p_k,   g_k);
    cudaGetSymbolAddress((void**)&p_v,   g_v);
    cudaGetSymbolAddress((void**)&p_att, g_att);
    cudaGetSymbolAddress((void**)&p_y2,  g_y2);
    cudaGetSymbolAddress((void**)&p_u,   g_u);

    // 1. LN1 + shift + window partition
    ln1_window_kernel<<<MTOK, 256>>>(x, g1, b1, p_h);

    // 2. Q/K/V projections (tf32 tensor cores)
    tgemm<false, false><<<dim3(CD / 128, MTOK / 128), 256>>>(p_h, wq, bq, nullptr, p_q, MTOK, CD, CD);
    tgemm<false, false><<<dim3(CD / 128, MTOK / 128), 256>>>(p_h, wk, bk, nullptr, p_k, MTOK, CD, CD);
    tgemm<false, false><<<dim3(CD / 128, MTOK / 128), 256>>>(p_h, wv, bv, nullptr, p_v, MTOK, CD, CD);

    // 3. windowed attention (bias + mask + softmax fused)
    attn_kernel<<<NWIN * 8, 256>>>(p_q, p_k, p_v, tbl, p_att);

    // 4. reverse window/roll + residual + LN2
    unwin_res_ln2<<<MTOK, 256>>>(x, p_att, g2, b2, p_y2);

    // 5. MLP: fc1 + exact GELU, then fc2 + residual (writes final output)
    tgemm<true,  false><<<dim3(HIDDEN / 128, MTOK / 128), 256>>>(p_y2, wf1, bf1, nullptr, p_u, MTOK, HIDDEN, CD);
    tgemm<false, true ><<<dim3(CD / 128, MTOK / 128), 256>>>(p_u, wf2, bf2, p_y2, out, MTOK, CD, HIDDEN);
}

// round 7
// speedup vs baseline: 2.3789x; 1.1801x over previous
#include <cuda_runtime.h>
#include <math.h>
#include <stdint.h>

// Problem constants (hardcoded per reference: B=2, H=W=256, C=256, NH=8, WS=8, SHIFT=4)
#define MTOK   131072          // B * H * W tokens
#define CD     256
#define NWIN   2048            // B * (H/8)*(W/8)
#define HIDDEN 1024

// ---------------- static scratch (no runtime allocation allowed) ----------------
__device__ float g_h   [(size_t)MTOK * CD];       // LN1 output, window-partitioned order
__device__ float g_qkv [(size_t)MTOK * 768];      // fused QKV output (stride 768)
__device__ float g_att [(size_t)MTOK * CD];       // attn output, [bw][head][n][d]
__device__ float g_y2  [(size_t)MTOK * CD];       // LN2 output (second-residual source)
__device__ float g_u   [(size_t)MTOK * HIDDEN];   // fc1+gelu output
// pre-transposed weights (row-major [N][K], k contiguous)
__device__ float g_wt_qkv[768 * 256];
__device__ float g_wt_f1 [1024 * 256];
__device__ float g_wt_f2 [256 * 1024];
__device__ float g_bqkv  [768];

// ---------------- block-wide (256-thread) dual reduction ----------------
__device__ __forceinline__ void blockReduce2(float& a, float& b) {
    __shared__ float sa[8], sb[8];
    int lane = threadIdx.x & 31, wid = threadIdx.x >> 5;
#pragma unroll
    for (int o = 16; o; o >>= 1) {
        a += __shfl_xor_sync(0xffffffffu, a, o);
        b += __shfl_xor_sync(0xffffffffu, b, o);
    }
    if (lane == 0) { sa[wid] = a; sb[wid] = b; }
    __syncthreads();
    a = 0.f; b = 0.f;
#pragma unroll
    for (int i = 0; i < 8; i++) { a += sa[i]; b += sb[i]; }
}

// ---------------- weight transpose: src [R][Cc] -> dst [Cc][R] ----------------
__global__ void transpose_k(const float* __restrict__ src, float* __restrict__ dst,
                            int R, int Cc) {
    __shared__ float t[32][33];
    int bx = blockIdx.x * 32, by = blockIdx.y * 32;
    int x = bx + threadIdx.x;
#pragma unroll
    for (int i = 0; i < 32; i += 8) {
        int y = by + threadIdx.y + i;
        t[threadIdx.y + i][threadIdx.x] = src[(size_t)y * Cc + x];
    }
    __syncthreads();
    int x2 = by + threadIdx.x;
#pragma unroll
    for (int i = 0; i < 32; i += 8) {
        int y2 = bx + threadIdx.y + i;
        dst[(size_t)y2 * R + x2] = t[threadIdx.x][threadIdx.y + i];
    }
}

__global__ void pack_bias_qkv(const float* __restrict__ bq, const float* __restrict__ bk,
                              const float* __restrict__ bv, float* __restrict__ bqkv) {
    int t = threadIdx.x;
    bqkv[t]       = bq[t];
    bqkv[256 + t] = bk[t];
    bqkv[512 + t] = bv[t];
}

// ---------------- kernel 1: LN1 fused with shift-roll + window partition ----------------
__global__ void ln1_window_kernel(const float* __restrict__ x,
                                  const float* __restrict__ g1,
                                  const float* __restrict__ b1,
                                  float* __restrict__ h) {
    int m = blockIdx.x;
    int tid = threadIdx.x;                 // 256 threads = channels
    int bw = m >> 6, n = m & 63;
    int bb = bw >> 10, widx = bw & 1023;
    int wh = widx >> 5, ww = widx & 31;
    int r = n >> 3, c = n & 7;
    int gh = (wh * 8 + r + 4) & 255;       // roll(x, -4)
    int gw = (ww * 8 + c + 4) & 255;
    const float* row = x + ((size_t)bb * 65536 + (size_t)gh * 256 + gw) * CD;
    float v = row[tid];
    float a = v, b = v * v;
    blockReduce2(a, b);
    float mu = a * (1.0f / CD);
    float var = b * (1.0f / CD) - mu * mu;
    float rstd = rsqrtf(var + 1e-5f);
    h[(size_t)m * CD + tid] = (v - mu) * rstd * g1[tid] + b1[tid];
}

// ---------------- tf32 tensor-core GEMM, cp.async 4-stage pipeline ----------------
__device__ __forceinline__ void ldsm4(uint32_t& r0, uint32_t& r1, uint32_t& r2, uint32_t& r3,
                                      uint32_t addr) {
    asm volatile("ldmatrix.sync.aligned.m8n8.x4.shared.b16 {%0,%1,%2,%3}, [%4];"
                 : "=r"(r0), "=r"(r1), "=r"(r2), "=r"(r3) : "r"(addr));
}
__device__ __forceinline__ void mma_tf32(float* c, const uint32_t* a, const uint32_t* b) {
    asm volatile(
        "mma.sync.aligned.m16n8k8.row.col.f32.tf32.tf32.f32 "
        "{%0,%1,%2,%3}, {%4,%5,%6,%7}, {%8,%9}, {%0,%1,%2,%3};"
        : "+f"(c[0]), "+f"(c[1]), "+f"(c[2]), "+f"(c[3])
        : "r"(a[0]), "r"(a[1]), "r"(a[2]), "r"(a[3]), "r"(b[0]), "r"(b[1]));
}
#define CP_COMMIT() asm volatile("cp.async.commit_group;")

#define STAGES 4
#define STAGE_U32 8192                    // 2 x 128x32 floats per stage
#define SMEM_BYTES (STAGES * STAGE_U32 * 4)

// one stage fill: 4 x 16B cp.async per thread per operand (A and Bt symmetric)
__device__ __forceinline__ void fill_stage(uint32_t sA, uint32_t sB,
                                           const float* __restrict__ A,
                                           const float* __restrict__ Bt,
                                           int m0, int n0, int K, int k0, int tid) {
#pragma unroll
    for (int i = 0; i < 4; i++) {
        int idx = tid + 256 * i;
        int rm = idx >> 3, kq = idx & 7;
        uint32_t doff = (uint32_t)((rm * 32 + ((kq ^ (rm & 7)) << 2)) << 2);
        const float* ga = A + (size_t)(m0 + rm) * K + k0 + kq * 4;
        asm volatile("cp.async.cg.shared.global [%0], [%1], 16;" :: "r"(sA + doff), "l"(ga));
        const float* gb = Bt + (size_t)(n0 + rm) * K + k0 + kq * 4;
        asm volatile("cp.async.cg.shared.global [%0], [%1], 16;" :: "r"(sB + doff), "l"(gb));
    }
}

// C[M,Nn] = A[M,K] @ Bt[Nn,K]^T + bias (+ optional exact GELU, + optional residual)
// BM=BN=128, BK=32; 8 warps (4m x 2n), warp tile 32x64 = 2x8 m16n8k8 frags.
template <bool GELU, bool RES>
__global__ void __launch_bounds__(256)
tgemm(const float* __restrict__ A, const float* __restrict__ Bt,
      const float* __restrict__ bias, const float* __restrict__ res,
      float* __restrict__ C, int M, int Nn, int K) {
    extern __shared__ __align__(16) uint32_t smem[];
    int tid = threadIdx.x;
    int lane = tid & 31, wid = tid >> 5;
    int wm = wid >> 1, wn = wid & 1;
    int m0 = blockIdx.y * 128, n0 = blockIdx.x * 128;

    uint32_t base = (uint32_t)__cvta_generic_to_shared(smem);

    float acc[2][8][4] = {};
    const int NITER = K >> 5;

#pragma unroll
    for (int s = 0; s < STAGES - 1; s++) {
        uint32_t sA = base + s * (STAGE_U32 * 4);
        fill_stage(sA, sA + 16384, A, Bt, m0, n0, K, s * 32, tid);
        CP_COMMIT();
    }

    int r = lane & 7, quad = lane >> 3;
    for (int it = 0; it < NITER; it++) {
        asm volatile("cp.async.wait_group %0;" :: "n"(STAGES - 2));
        __syncthreads();

        int nt_tile = it + STAGES - 1;
        if (nt_tile < NITER) {
            uint32_t sA = base + (nt_tile % STAGES) * (STAGE_U32 * 4);
            fill_stage(sA, sA + 16384, A, Bt, m0, n0, K, nt_tile * 32, tid);
        }
        CP_COMMIT();

        uint32_t sA = base + (it % STAGES) * (STAGE_U32 * 4);
        uint32_t sB = sA + 16384;
#pragma unroll
        for (int kk = 0; kk < 4; kk++) {
            uint32_t af[2][4];
#pragma unroll
            for (int mt = 0; mt < 2; mt++) {
                int row = wm * 32 + mt * 16 + ((quad & 1) << 3) + r;
                int grp = ((kk << 1) | (quad >> 1)) ^ (row & 7);
                ldsm4(af[mt][0], af[mt][1], af[mt][2], af[mt][3],
                      sA + ((row * 32 + grp * 4) << 2));
            }
            uint32_t bf[8][2];
#pragma unroll
            for (int p = 0; p < 4; p++) {
                int nn = wn * 64 + p * 16 + ((quad >> 1) << 3) + r;
                int grp = ((kk << 1) | (quad & 1)) ^ (nn & 7);
                ldsm4(bf[2 * p][0], bf[2 * p][1], bf[2 * p + 1][0], bf[2 * p + 1][1],
                      sB + ((nn * 32 + grp * 4) << 2));
            }
#pragma unroll
            for (int mt = 0; mt < 2; mt++)
#pragma unroll
                for (int nt = 0; nt < 8; nt++)
                    mma_tf32(acc[mt][nt], af[mt], bf[nt]);
        }
    }

    // epilogue: d0 (r,c), d1 (r,c+1), d2 (r+8,c), d3 (r+8,c+1); r=lane/4, c=(lane%4)*2
    int r0 = lane >> 2, c0 = (lane & 3) << 1;
#pragma unroll
    for (int mt = 0; mt < 2; mt++) {
#pragma unroll
        for (int half = 0; half < 2; half++) {
            int row = m0 + wm * 32 + mt * 16 + half * 8 + r0;
#pragma unroll
            for (int nt = 0; nt < 8; nt++) {
                int col = n0 + wn * 64 + nt * 8 + c0;
                float v0 = acc[mt][nt][half * 2 + 0] + bias[col];
                float v1 = acc[mt][nt][half * 2 + 1] + bias[col + 1];
                if (GELU) {
                    v0 = 0.5f * v0 * (1.0f + erff(v0 * 0.70710678118654752f));
                    v1 = 0.5f * v1 * (1.0f + erff(v1 * 0.70710678118654752f));
                }
                if (RES) {
                    v0 += res[(size_t)row * Nn + col];
                    v1 += res[(size_t)row * Nn + col + 1];
                }
                *(float2*)&C[(size_t)row * Nn + col] = make_float2(v0, v1);
            }
        }
    }
}

// ---------------- kernel 3: windowed attention, one block per (window, head) ----------------
// reads fused qkv buffer: row stride 768, q at +0, k at +256, v at +512
__global__ void attn_kernel(const float* __restrict__ qkv,
                            const float* __restrict__ bias_table,
                            float* __restrict__ attn_out) {
    int blk = blockIdx.x;               // bw*8 + head
    int bw = blk >> 3, head = blk & 7;
    int widx = bw & 1023;
    int wh = widx >> 5, ww = widx & 31;
    int tid = threadIdx.x;              // 256 threads

    __shared__ float sq[64][33];
    __shared__ float sk[64][33];
    __shared__ float sv[64][36];        // stride multiple of 4 for float4 reads
    __shared__ float sc[64][65];
    __shared__ int   lab[64];

    // load q,k,v head-slices: 64x32 each; thread -> (n = tid/4, d0 = (tid%4)*8)
    {
        int n = tid >> 2, d0 = (tid & 3) << 3;
        size_t off = ((size_t)bw * 64 + n) * 768 + head * 32 + d0;
        float4 a0 = *(const float4*)(qkv + off);
        float4 a1 = *(const float4*)(qkv + off + 4);
        sq[n][d0 + 0] = a0.x; sq[n][d0 + 1] = a0.y; sq[n][d0 + 2] = a0.z; sq[n][d0 + 3] = a0.w;
        sq[n][d0 + 4] = a1.x; sq[n][d0 + 5] = a1.y; sq[n][d0 + 6] = a1.z; sq[n][d0 + 7] = a1.w;
        float4 c0 = *(const float4*)(qkv + off + 256);
        float4 c1 = *(const float4*)(qkv + off + 260);
        sk[n][d0 + 0] = c0.x; sk[n][d0 + 1] = c0.y; sk[n][d0 + 2] = c0.z; sk[n][d0 + 3] = c0.w;
        sk[n][d0 + 4] = c1.x; sk[n][d0 + 5] = c1.y; sk[n][d0 + 6] = c1.z; sk[n][d0 + 7] = c1.w;
        float4 v0 = *(const float4*)(qkv + off + 512);
        float4 v1 = *(const float4*)(qkv + off + 516);
        *(float4*)&sv[n][d0]     = v0;
        *(float4*)&sv[n][d0 + 4] = v1;
    }
    // region labels for shift mask
    if (tid < 64) {
        int ri = tid >> 3, ci = tid & 7;
        int srow = wh * 8 + ri, scol = ww * 8 + ci;
        int lh = (srow < 248) ? 0 : ((srow < 252) ? 1 : 2);
        int lw = (scol < 248) ? 0 : ((scol < 252) ? 1 : 2);
        lab[tid] = lh * 3 + lw;
    }
    __syncthreads();

    // scores: 16x16 thread grid, each computes a 4x4 tile of the 64x64 score matrix
    {
        int i0 = (tid >> 4) << 2, j0 = (tid & 15) << 2;
        float accs[4][4] = {};
#pragma unroll 8
        for (int d = 0; d < 32; d++) {
            float a0 = sq[i0 + 0][d], a1 = sq[i0 + 1][d], a2 = sq[i0 + 2][d], a3 = sq[i0 + 3][d];
            float b0 = sk[j0 + 0][d], b1 = sk[j0 + 1][d], b2 = sk[j0 + 2][d], b3 = sk[j0 + 3][d];
            accs[0][0] += a0 * b0; accs[0][1] += a0 * b1; accs[0][2] += a0 * b2; accs[0][3] += a0 * b3;
            accs[1][0] += a1 * b0; accs[1][1] += a1 * b1; accs[1][2] += a1 * b2; accs[1][3] += a1 * b3;
            accs[2][0] += a2 * b0; accs[2][1] += a2 * b1; accs[2][2] += a2 * b2; accs[2][3] += a2 * b3;
            accs[3][0] += a3 * b0; accs[3][1] += a3 * b1; accs[3][2] += a3 * b2; accs[3][3] += a3 * b3;
        }
        const float sscale = 0.17677669529663687f;  // 1/sqrt(32)
#pragma unroll
        for (int ii = 0; ii < 4; ii++) {
            int i = i0 + ii;
            int ri = i >> 3, ci = i & 7, li = lab[i];
#pragma unroll
            for (int jj = 0; jj < 4; jj++) {
                int j = j0 + jj;
                int rj = j >> 3, cj = j & 7;
                int rel = (ri - rj + 7) * 15 + (ci - cj + 7);
                float s = accs[ii][jj] * sscale + bias_table[rel * 8 + head];
                if (li != lab[j]) s -= 100.0f;
                sc[i][j] = s;
            }
        }
    }
    __syncthreads();

    // softmax: 4 threads per row (sub-group shuffles)
    {
        int row = tid >> 2, sub = tid & 3;
        float mx = -1e30f;
#pragma unroll
        for (int t = 0; t < 16; t++) mx = fmaxf(mx, sc[row][sub * 16 + t]);
        mx = fmaxf(mx, __shfl_xor_sync(0xffffffffu, mx, 1));
        mx = fmaxf(mx, __shfl_xor_sync(0xffffffffu, mx, 2));
        float sum = 0.f;
#pragma unroll
        for (int t = 0; t < 16; t++) {
            float e = __expf(sc[row][sub * 16 + t] - mx);
            sc[row][sub * 16 + t] = e;
            sum += e;
        }
        sum += __shfl_xor_sync(0xffffffffu, sum, 1);
        sum += __shfl_xor_sync(0xffffffffu, sum, 2);
        float inv = 1.0f / sum;
#pragma unroll
        for (int t = 0; t < 16; t++) sc[row][sub * 16 + t] *= inv;
    }
    __syncthreads();

    // out = attn @ v : thread -> (i = tid/4, d0 = (tid%4)*8)
    {
        int i = tid >> 2, d0 = (tid & 3) << 3;
        float acc[8] = {};
#pragma unroll 16
        for (int j = 0; j < 64; j++) {
            float s = sc[i][j];
            float4 v0 = *(const float4*)&sv[j][d0];
            float4 v1 = *(const float4*)&sv[j][d0 + 4];
            acc[0] += s * v0.x; acc[1] += s * v0.y; acc[2] += s * v0.z; acc[3] += s * v0.w;
            acc[4] += s * v1.x; acc[5] += s * v1.y; acc[6] += s * v1.z; acc[7] += s * v1.w;
        }
        size_t o = (((size_t)bw * 8 + head) * 64 + i) * 32 + d0;
        float4 o0 = {acc[0], acc[1], acc[2], acc[3]};
        float4 o1 = {acc[4], acc[5], acc[6], acc[7]};
        *(float4*)&attn_out[o]     = o0;
        *(float4*)&attn_out[o + 4] = o1;
    }
}

// ---------------- kernel 4: un-window + un-roll + residual + LN2 ----------------
__global__ void unwin_res_ln2(const float* __restrict__ x, const float* __restrict__ att,
                              const float* __restrict__ g2, const float* __restrict__ b2,
                              float* __restrict__ y2) {
    int m = blockIdx.x;
    int ch = threadIdx.x;
    int bb = m >> 16, l = m & 65535;
    int gh = l >> 8, gw = l & 255;
    int sh = (gh + 252) & 255, sw = (gw + 252) & 255;   // roll(+4) inverse
    int wh = sh >> 3, r = sh & 7, ww = sw >> 3, c = sw & 7;
    size_t base = ((size_t)((bb * 1024 + wh * 32 + ww) * 8 + r) * 64 + (size_t)c * 8) * 32;
    float v = x[(size_t)m * CD + ch] + att[base + ch];
    float a = v, b = v * v;
    blockReduce2(a, b);
    float mu = a * (1.0f / CD);
    float var = b * (1.0f / CD) - mu * mu;
    float rstd = rsqrtf(var + 1e-5f);
    y2[(size_t)m * CD + ch] = (v - mu) * rstd * g2[ch] + b2[ch];
}

// ---------------- host launch ----------------
extern "C" void kernel_launch(void* const* d_in, const int* in_sizes, int n_in,
                              void* d_out, int out_size) {
    (void)in_sizes; (void)n_in; (void)out_size;
    const float* x    = (const float*)d_in[0];
    const float* g1   = (const float*)d_in[1];
    const float* b1   = (const float*)d_in[2];
    const float* wq   = (const float*)d_in[3];
    const float* bq   = (const float*)d_in[4];
    const float* wk   = (const float*)d_in[5];
    const float* bk   = (const float*)d_in[6];
    const float* wv   = (const float*)d_in[7];
    const float* bv   = (const float*)d_in[8];
    const float* tbl  = (const float*)d_in[9];
    const float* g2   = (const float*)d_in[10];
    const float* b2   = (const float*)d_in[11];
    const float* wf1  = (const float*)d_in[12];
    const float* bf1  = (const float*)d_in[13];
    const float* wf2  = (const float*)d_in[14];
    const float* bf2  = (const float*)d_in[15];
    float* out = (float*)d_out;

    float *p_h, *p_qkv, *p_att, *p_y2, *p_u, *p_wtqkv, *p_wtf1, *p_wtf2, *p_bqkv;
    cudaGetSymbolAddress((void**)&p_h,     g_h);
    cudaGetSymbolAddress((void**)&p_qkv,   g_qkv);
    cudaGetSymbolAddress((void**)&p_att,   g_att);
    cudaGetSymbolAddress((void**)&p_y2,    g_y2);
    cudaGetSymbolAddress((void**)&p_u,     g_u);
    cudaGetSymbolAddress((void**)&p_wtqkv, g_wt_qkv);
    cudaGetSymbolAddress((void**)&p_wtf1,  g_wt_f1);
    cudaGetSymbolAddress((void**)&p_wtf2,  g_wt_f2);
    cudaGetSymbolAddress((void**)&p_bqkv,  g_bqkv);

    static bool attr_done = false;
    if (!attr_done) {
        cudaFuncSetAttribute(tgemm<false, false>, cudaFuncAttributeMaxDynamicSharedMemorySize, SMEM_BYTES);
        cudaFuncSetAttribute(tgemm<true,  false>, cudaFuncAttributeMaxDynamicSharedMemorySize, SMEM_BYTES);
        cudaFuncSetAttribute(tgemm<false, true >, cudaFuncAttributeMaxDynamicSharedMemorySize, SMEM_BYTES);
        attr_done = true;
    }

    dim3 t32(32, 8);
    // 0. pack transposed weights + fused qkv bias
    transpose_k<<<dim3(8, 8),  t32>>>(wq,  p_wtqkv,           256, 256);
    transpose_k<<<dim3(8, 8),  t32>>>(wk,  p_wtqkv + 65536,   256, 256);
    transpose_k<<<dim3(8, 8),  t32>>>(wv,  p_wtqkv + 131072,  256, 256);
    transpose_k<<<dim3(32, 8), t32>>>(wf1, p_wtf1,            256, 1024);
    transpose_k<<<dim3(8, 32), t32>>>(wf2, p_wtf2,            1024, 256);
    pack_bias_qkv<<<1, 256>>>(bq, bk, bv, p_bqkv);

    // 1. LN1 + shift + window partition
    ln1_window_kernel<<<MTOK, 256>>>(x, g1, b1, p_h);

    // 2. fused QKV projection (tf32 tensor cores, cp.async pipeline)
    tgemm<false, false><<<dim3(768 / 128, MTOK / 128), 256, SMEM_BYTES>>>(
        p_h, p_wtqkv, p_bqkv, nullptr, p_qkv, MTOK, 768, CD);

    // 3. windowed attention (bias + mask + softmax fused)
    attn_kernel<<<NWIN * 8, 256>>>(p_qkv, tbl, p_att);

    // 4. reverse window/roll + residual + LN2
    unwin_res_ln2<<<MTOK, 256>>>(x, p_att, g2, b2, p_y2);

    // 5. MLP: fc1 + exact GELU, then fc2 + residual (writes final output)
    tgemm<true,  false><<<dim3(HIDDEN / 128, MTOK / 128), 256, SMEM_BYTES>>>(
        p_y2, p_wtf1, bf1, nullptr, p_u, MTOK, HIDDEN, CD);
    tgemm<false, true ><<<dim3(CD / 128, MTOK / 128), 256, SMEM_BYTES>>>(
        p_u, p_wtf2, bf2, p_y2, out, MTOK, CD, HIDDEN);
}

// round 11
// speedup vs baseline: 2.9541x; 1.2418x over previous
#include <cuda_runtime.h>
#include <math.h>
#include <stdint.h>

// Problem constants (hardcoded per reference: B=2, H=W=256, C=256, NH=8, WS=8, SHIFT=4)
#define MTOK   131072          // B * H * W tokens
#define CD     256
#define NWIN   2048            // B * (H/8)*(W/8)
#define HIDDEN 1024

// ---------------- static scratch (no runtime allocation allowed) ----------------
__device__ float g_h   [(size_t)MTOK * CD];       // LN1 output, window-partitioned order
__device__ float g_qkv [(size_t)MTOK * 768];      // fused QKV output (stride 768)
__device__ float g_att [(size_t)MTOK * CD];       // attn output, [bw][head][n][d]
__device__ float g_y2  [(size_t)MTOK * CD];       // LN2 output (second-residual source)
__device__ float g_u   [(size_t)MTOK * HIDDEN];   // fc1+gelu output
// pre-transposed weights (row-major [N][K], k contiguous)
__device__ float g_wt_qkv[768 * 256];
__device__ float g_wt_f1 [1024 * 256];
__device__ float g_wt_f2 [256 * 1024];
__device__ float g_bqkv  [768];

// ---------------- weight transpose: src [R][Cc] -> dst [Cc][R] ----------------
__global__ void transpose_k(const float* __restrict__ src, float* __restrict__ dst,
                            int R, int Cc) {
    __shared__ float t[32][33];
    int bx = blockIdx.x * 32, by = blockIdx.y * 32;
    int x = bx + threadIdx.x;
#pragma unroll
    for (int i = 0; i < 32; i += 8) {
        int y = by + threadIdx.y + i;
        t[threadIdx.y + i][threadIdx.x] = src[(size_t)y * Cc + x];
    }
    __syncthreads();
    int x2 = by + threadIdx.x;
#pragma unroll
    for (int i = 0; i < 32; i += 8) {
        int y2 = bx + threadIdx.y + i;
        dst[(size_t)y2 * R + x2] = t[threadIdx.x][threadIdx.y + i];
    }
}

__global__ void pack_bias_qkv(const float* __restrict__ bq, const float* __restrict__ bk,
                              const float* __restrict__ bv, float* __restrict__ bqkv) {
    int t = threadIdx.x;
    bqkv[t]       = bq[t];
    bqkv[256 + t] = bk[t];
    bqkv[512 + t] = bv[t];
}

// ---------------- warp-level dual reduction (sum, sumsq) ----------------
__device__ __forceinline__ void warpReduce2(float& a, float& b) {
#pragma unroll
    for (int o = 16; o; o >>= 1) {
        a += __shfl_xor_sync(0xffffffffu, a, o);
        b += __shfl_xor_sync(0xffffffffu, b, o);
    }
}

// ---------------- kernel 1: LN1 fused with shift-roll + window partition ----------------
// one warp per output row; lane holds 8 channels (2 x float4)
__global__ void ln1_window_kernel(const float* __restrict__ x,
                                  const float* __restrict__ g1,
                                  const float* __restrict__ b1,
                                  float* __restrict__ h) {
    int m = blockIdx.x * 8 + (threadIdx.x >> 5);
    int lane = threadIdx.x & 31;
    int bw = m >> 6, n = m & 63;
    int bb = bw >> 10, widx = bw & 1023;
    int wh = widx >> 5, ww = widx & 31;
    int r = n >> 3, c = n & 7;
    int gh = (wh * 8 + r + 4) & 255;       // roll(x, -4)
    int gw = (ww * 8 + c + 4) & 255;
    const float* row = x + ((size_t)bb * 65536 + (size_t)gh * 256 + gw) * CD;
    int ch = lane * 8;
    float4 v0 = *(const float4*)(row + ch);
    float4 v1 = *(const float4*)(row + ch + 4);
    float a = v0.x + v0.y + v0.z + v0.w + v1.x + v1.y + v1.z + v1.w;
    float b = v0.x * v0.x + v0.y * v0.y + v0.z * v0.z + v0.w * v0.w
            + v1.x * v1.x + v1.y * v1.y + v1.z * v1.z + v1.w * v1.w;
    warpReduce2(a, b);
    float mu = a * (1.0f / CD);
    float var = b * (1.0f / CD) - mu * mu;
    float rstd = rsqrtf(var + 1e-5f);
    float4 ga = *(const float4*)(g1 + ch);
    float4 gb = *(const float4*)(g1 + ch + 4);
    float4 ba = *(const float4*)(b1 + ch);
    float4 bbv = *(const float4*)(b1 + ch + 4);
    float4 o0, o1;
    o0.x = (v0.x - mu) * rstd * ga.x + ba.x;
    o0.y = (v0.y - mu) * rstd * ga.y + ba.y;
    o0.z = (v0.z - mu) * rstd * ga.z + ba.z;
    o0.w = (v0.w - mu) * rstd * ga.w + ba.w;
    o1.x = (v1.x - mu) * rstd * gb.x + bbv.x;
    o1.y = (v1.y - mu) * rstd * gb.y + bbv.y;
    o1.z = (v1.z - mu) * rstd * gb.z + bbv.z;
    o1.w = (v1.w - mu) * rstd * gb.w + bbv.w;
    float* dst = h + (size_t)m * CD + ch;
    *(float4*)dst = o0;
    *(float4*)(dst + 4) = o1;
}

// ---------------- tf32 tensor-core GEMM, cp.async 3-stage pipeline, 2 CTAs/SM ----------------
__device__ __forceinline__ void ldsm4(uint32_t& r0, uint32_t& r1, uint32_t& r2, uint32_t& r3,
                                      uint32_t addr) {
    asm volatile("ldmatrix.sync.aligned.m8n8.x4.shared.b16 {%0,%1,%2,%3}, [%4];"
                 : "=r"(r0), "=r"(r1), "=r"(r2), "=r"(r3) : "r"(addr));
}
__device__ __forceinline__ void mma_tf32(float* c, const uint32_t* a, const uint32_t* b) {
    asm volatile(
        "mma.sync.aligned.m16n8k8.row.col.f32.tf32.tf32.f32 "
        "{%0,%1,%2,%3}, {%4,%5,%6,%7}, {%8,%9}, {%0,%1,%2,%3};"
        : "+f"(c[0]), "+f"(c[1]), "+f"(c[2]), "+f"(c[3])
        : "r"(a[0]), "r"(a[1]), "r"(a[2]), "r"(a[3]), "r"(b[0]), "r"(b[1]));
}
#define CP_COMMIT() asm volatile("cp.async.commit_group;")

#define STAGES 3
#define STAGE_U32 8192                    // 2 x 128x32 floats per stage
#define SMEM_BYTES (STAGES * STAGE_U32 * 4)

// one stage fill: 4 x 16B cp.async per thread per operand (A and Bt symmetric)
__device__ __forceinline__ void fill_stage(uint32_t sA, uint32_t sB,
                                           const float* __restrict__ A,
                                           const float* __restrict__ Bt,
                                           int m0, int n0, int K, int k0, int tid) {
#pragma unroll
    for (int i = 0; i < 4; i++) {
        int idx = tid + 256 * i;
        int rm = idx >> 3, kq = idx & 7;
        uint32_t doff = (uint32_t)((rm * 32 + ((kq ^ (rm & 7)) << 2)) << 2);
        const float* ga = A + (size_t)(m0 + rm) * K + k0 + kq * 4;
        asm volatile("cp.async.cg.shared.global [%0], [%1], 16;" :: "r"(sA + doff), "l"(ga));
        const float* gb = Bt + (size_t)(n0 + rm) * K + k0 + kq * 4;
        asm volatile("cp.async.cg.shared.global [%0], [%1], 16;" :: "r"(sB + doff), "l"(gb));
    }
}

// C[M,Nn] = A[M,K] @ Bt[Nn,K]^T + bias (+ optional exact GELU, + optional residual)
// BM=BN=128, BK=32; 8 warps (4m x 2n), warp tile 32x64 = 2x8 m16n8k8 frags.
template <bool GELU, bool RES>
__global__ void __launch_bounds__(256, 2)
tgemm(const float* __restrict__ A, const float* __restrict__ Bt,
      const float* __restrict__ bias, const float* __restrict__ res,
      float* __restrict__ C, int M, int Nn, int K) {
    extern __shared__ __align__(16) uint32_t smem[];
    int tid = threadIdx.x;
    int lane = tid & 31, wid = tid >> 5;
    int wm = wid >> 1, wn = wid & 1;
    int m0 = blockIdx.y * 128, n0 = blockIdx.x * 128;

    uint32_t base = (uint32_t)__cvta_generic_to_shared(smem);

    float acc[2][8][4] = {};
    const int NITER = K >> 5;

#pragma unroll
    for (int s = 0; s < STAGES - 1; s++) {
        uint32_t sA = base + s * (STAGE_U32 * 4);
        fill_stage(sA, sA + 16384, A, Bt, m0, n0, K, s * 32, tid);
        CP_COMMIT();
    }

    int r = lane & 7, quad = lane >> 3;
    for (int it = 0; it < NITER; it++) {
        asm volatile("cp.async.wait_group %0;" :: "n"(STAGES - 2));
        __syncthreads();

        int nt_tile = it + STAGES - 1;
        if (nt_tile < NITER) {
            uint32_t sA = base + (nt_tile % STAGES) * (STAGE_U32 * 4);
            fill_stage(sA, sA + 16384, A, Bt, m0, n0, K, nt_tile * 32, tid);
        }
        CP_COMMIT();

        uint32_t sA = base + (it % STAGES) * (STAGE_U32 * 4);
        uint32_t sB = sA + 16384;
#pragma unroll
        for (int kk = 0; kk < 4; kk++) {
            uint32_t af[2][4];
#pragma unroll
            for (int mt = 0; mt < 2; mt++) {
                int row = wm * 32 + mt * 16 + ((quad & 1) << 3) + r;
                int grp = ((kk << 1) | (quad >> 1)) ^ (row & 7);
                ldsm4(af[mt][0], af[mt][1], af[mt][2], af[mt][3],
                      sA + ((row * 32 + grp * 4) << 2));
            }
            uint32_t bf[8][2];
#pragma unroll
            for (int p = 0; p < 4; p++) {
                int nn = wn * 64 + p * 16 + ((quad >> 1) << 3) + r;
                int grp = ((kk << 1) | (quad & 1)) ^ (nn & 7);
                ldsm4(bf[2 * p][0], bf[2 * p][1], bf[2 * p + 1][0], bf[2 * p + 1][1],
                      sB + ((nn * 32 + grp * 4) << 2));
            }
#pragma unroll
            for (int mt = 0; mt < 2; mt++)
#pragma unroll
                for (int nt = 0; nt < 8; nt++)
                    mma_tf32(acc[mt][nt], af[mt], bf[nt]);
        }
    }

    // epilogue: d0 (r,c), d1 (r,c+1), d2 (r+8,c), d3 (r+8,c+1); r=lane/4, c=(lane%4)*2
    int r0 = lane >> 2, c0 = (lane & 3) << 1;
#pragma unroll
    for (int mt = 0; mt < 2; mt++) {
#pragma unroll
        for (int half = 0; half < 2; half++) {
            int row = m0 + wm * 32 + mt * 16 + half * 8 + r0;
#pragma unroll
            for (int nt = 0; nt < 8; nt++) {
                int col = n0 + wn * 64 + nt * 8 + c0;
                float v0 = acc[mt][nt][half * 2 + 0] + bias[col];
                float v1 = acc[mt][nt][half * 2 + 1] + bias[col + 1];
                if (GELU) {
                    v0 = 0.5f * v0 * (1.0f + erff(v0 * 0.70710678118654752f));
                    v1 = 0.5f * v1 * (1.0f + erff(v1 * 0.70710678118654752f));
                }
                if (RES) {
                    v0 += res[(size_t)row * Nn + col];
                    v1 += res[(size_t)row * Nn + col + 1];
                }
                *(float2*)&C[(size_t)row * Nn + col] = make_float2(v0, v1);
            }
        }
    }
}

// ---------------- kernel 3: windowed attention, one block per (window, head) ----------------
// reads fused qkv buffer: row stride 768, q at +0, k at +256, v at +512
__global__ void attn_kernel(const float* __restrict__ qkv,
                            const float* __restrict__ bias_table,
                            float* __restrict__ attn_out) {
    int blk = blockIdx.x;               // bw*8 + head
    int bw = blk >> 3, head = blk & 7;
    int widx = bw & 1023;
    int wh = widx >> 5, ww = widx & 31;
    int tid = threadIdx.x;              // 256 threads

    __shared__ float sq[64][33];
    __shared__ float sk[64][33];
    __shared__ float sv[64][36];        // stride multiple of 4 for float4 reads
    __shared__ float sc[64][65];
    __shared__ int   lab[64];

    // load q,k,v head-slices: 64x32 each; thread -> (n = tid/4, d0 = (tid%4)*8)
    {
        int n = tid >> 2, d0 = (tid & 3) << 3;
        size_t off = ((size_t)bw * 64 + n) * 768 + head * 32 + d0;
        float4 a0 = *(const float4*)(qkv + off);
        float4 a1 = *(const float4*)(qkv + off + 4);
        sq[n][d0 + 0] = a0.x; sq[n][d0 + 1] = a0.y; sq[n][d0 + 2] = a0.z; sq[n][d0 + 3] = a0.w;
        sq[n][d0 + 4] = a1.x; sq[n][d0 + 5] = a1.y; sq[n][d0 + 6] = a1.z; sq[n][d0 + 7] = a1.w;
        float4 c0 = *(const float4*)(qkv + off + 256);
        float4 c1 = *(const float4*)(qkv + off + 260);
        sk[n][d0 + 0] = c0.x; sk[n][d0 + 1] = c0.y; sk[n][d0 + 2] = c0.z; sk[n][d0 + 3] = c0.w;
        sk[n][d0 + 4] = c1.x; sk[n][d0 + 5] = c1.y; sk[n][d0 + 6] = c1.z; sk[n][d0 + 7] = c1.w;
        float4 v0 = *(const float4*)(qkv + off + 512);
        float4 v1 = *(const float4*)(qkv + off + 516);
        *(float4*)&sv[n][d0]     = v0;
        *(float4*)&sv[n][d0 + 4] = v1;
    }
    // region labels for shift mask
    if (tid < 64) {
        int ri = tid >> 3, ci = tid & 7;
        int srow = wh * 8 + ri, scol = ww * 8 + ci;
        int lh = (srow < 248) ? 0 : ((srow < 252) ? 1 : 2);
        int lw = (scol < 248) ? 0 : ((scol < 252) ? 1 : 2);
        lab[tid] = lh * 3 + lw;
    }
    __syncthreads();

    // scores: 16x16 thread grid, each computes a 4x4 tile of the 64x64 score matrix
    {
        int i0 = (tid >> 4) << 2, j0 = (tid & 15) << 2;
        float accs[4][4] = {};
#pragma unroll 8
        for (int d = 0; d < 32; d++) {
            float a0 = sq[i0 + 0][d], a1 = sq[i0 + 1][d], a2 = sq[i0 + 2][d], a3 = sq[i0 + 3][d];
            float b0 = sk[j0 + 0][d], b1 = sk[j0 + 1][d], b2 = sk[j0 + 2][d], b3 = sk[j0 + 3][d];
            accs[0][0] += a0 * b0; accs[0][1] += a0 * b1; accs[0][2] += a0 * b2; accs[0][3] += a0 * b3;
            accs[1][0] += a1 * b0; accs[1][1] += a1 * b1; accs[1][2] += a1 * b2; accs[1][3] += a1 * b3;
            accs[2][0] += a2 * b0; accs[2][1] += a2 * b1; accs[2][2] += a2 * b2; accs[2][3] += a2 * b3;
            accs[3][0] += a3 * b0; accs[3][1] += a3 * b1; accs[3][2] += a3 * b2; accs[3][3] += a3 * b3;
        }
        const float sscale = 0.17677669529663687f;  // 1/sqrt(32)
#pragma unroll
        for (int ii = 0; ii < 4; ii++) {
            int i = i0 + ii;
            int ri = i >> 3, ci = i & 7, li = lab[i];
#pragma unroll
            for (int jj = 0; jj < 4; jj++) {
                int j = j0 + jj;
                int rj = j >> 3, cj = j & 7;
                int rel = (ri - rj + 7) * 15 + (ci - cj + 7);
                float s = accs[ii][jj] * sscale + bias_table[rel * 8 + head];
                if (li != lab[j]) s -= 100.0f;
                sc[i][j] = s;
            }
        }
    }
    __syncthreads();

    // softmax: 4 threads per row (sub-group shuffles)
    {
        int row = tid >> 2, sub = tid & 3;
        float mx = -1e30f;
#pragma unroll
        for (int t = 0; t < 16; t++) mx = fmaxf(mx, sc[row][sub * 16 + t]);
        mx = fmaxf(mx, __shfl_xor_sync(0xffffffffu, mx, 1));
        mx = fmaxf(mx, __shfl_xor_sync(0xffffffffu, mx, 2));
        float sum = 0.f;
#pragma unroll
        for (int t = 0; t < 16; t++) {
            float e = __expf(sc[row][sub * 16 + t] - mx);
            sc[row][sub * 16 + t] = e;
            sum += e;
        }
        sum += __shfl_xor_sync(0xffffffffu, sum, 1);
        sum += __shfl_xor_sync(0xffffffffu, sum, 2);
        float inv = 1.0f / sum;
#pragma unroll
        for (int t = 0; t < 16; t++) sc[row][sub * 16 + t] *= inv;
    }
    __syncthreads();

    // out = attn @ v : thread -> (i = tid/4, d0 = (tid%4)*8)
    {
        int i = tid >> 2, d0 = (tid & 3) << 3;
        float acc[8] = {};
#pragma unroll 16
        for (int j = 0; j < 64; j++) {
            float s = sc[i][j];
            float4 v0 = *(const float4*)&sv[j][d0];
            float4 v1 = *(const float4*)&sv[j][d0 + 4];
            acc[0] += s * v0.x; acc[1] += s * v0.y; acc[2] += s * v0.z; acc[3] += s * v0.w;
            acc[4] += s * v1.x; acc[5] += s * v1.y; acc[6] += s * v1.z; acc[7] += s * v1.w;
        }
        size_t o = (((size_t)bw * 8 + head) * 64 + i) * 32 + d0;
        float4 o0 = {acc[0], acc[1], acc[2], acc[3]};
        float4 o1 = {acc[4], acc[5], acc[6], acc[7]};
        *(float4*)&attn_out[o]     = o0;
        *(float4*)&attn_out[o + 4] = o1;
    }
}

// ---------------- kernel 4: un-window + un-roll + residual + LN2 (warp per row) ----------------
__global__ void unwin_res_ln2(const float* __restrict__ x, const float* __restrict__ att,
                              const float* __restrict__ g2, const float* __restrict__ b2,
                              float* __restrict__ y2) {
    int m = blockIdx.x * 8 + (threadIdx.x >> 5);
    int lane = threadIdx.x & 31;
    int bb = m >> 16, l = m & 65535;
    int gh = l >> 8, gw = l & 255;
    int sh = (gh + 252) & 255, sw = (gw + 252) & 255;   // roll(+4) inverse
    int wh = sh >> 3, r = sh & 7, ww = sw >> 3, c = sw & 7;
    size_t base = ((size_t)((bb * 1024 + wh * 32 + ww) * 8 + r) * 64 + (size_t)c * 8) * 32;
    int ch = lane * 8;
    const float* xr = x + (size_t)m * CD + ch;
    const float* ar = att + base + ch;
    float4 x0 = *(const float4*)xr;
    float4 x1 = *(const float4*)(xr + 4);
    float4 a0 = *(const float4*)ar;
    float4 a1 = *(const float4*)(ar + 4);
    float4 v0 = {x0.x + a0.x, x0.y + a0.y, x0.z + a0.z, x0.w + a0.w};
    float4 v1 = {x1.x + a1.x, x1.y + a1.y, x1.z + a1.z, x1.w + a1.w};
    float a = v0.x + v0.y + v0.z + v0.w + v1.x + v1.y + v1.z + v1.w;
    float b = v0.x * v0.x + v0.y * v0.y + v0.z * v0.z + v0.w * v0.w
            + v1.x * v1.x + v1.y * v1.y + v1.z * v1.z + v1.w * v1.w;
    warpReduce2(a, b);
    float mu = a * (1.0f / CD);
    float var = b * (1.0f / CD) - mu * mu;
    float rstd = rsqrtf(var + 1e-5f);
    float4 ga = *(const float4*)(g2 + ch);
    float4 gb = *(const float4*)(g2 + ch + 4);
    float4 ba = *(const float4*)(b2 + ch);
    float4 bbv = *(const float4*)(b2 + ch + 4);
    float4 o0, o1;
    o0.x = (v0.x - mu) * rstd * ga.x + ba.x;
    o0.y = (v0.y - mu) * rstd * ga.y + ba.y;
    o0.z = (v0.z - mu) * rstd * ga.z + ba.z;
    o0.w = (v0.w - mu) * rstd * ga.w + ba.w;
    o1.x = (v1.x - mu) * rstd * gb.x + bbv.x;
    o1.y = (v1.y - mu) * rstd * gb.y + bbv.y;
    o1.z = (v1.z - mu) * rstd * gb.z + bbv.z;
    o1.w = (v1.w - mu) * rstd * gb.w + bbv.w;
    float* dst = y2 + (size_t)m * CD + ch;
    *(float4*)dst = o0;
    *(float4*)(dst + 4) = o1;
}

// ---------------- host launch ----------------
extern "C" void kernel_launch(void* const* d_in, const int* in_sizes, int n_in,
                              void* d_out, int out_size) {
    (void)in_sizes; (void)n_in; (void)out_size;
    const float* x    = (const float*)d_in[0];
    const float* g1   = (const float*)d_in[1];
    const float* b1   = (const float*)d_in[2];
    const float* wq   = (const float*)d_in[3];
    const float* bq   = (const float*)d_in[4];
    const float* wk   = (const float*)d_in[5];
    const float* bk   = (const float*)d_in[6];
    const float* wv   = (const float*)d_in[7];
    const float* bv   = (const float*)d_in[8];
    const float* tbl  = (const float*)d_in[9];
    const float* g2   = (const float*)d_in[10];
    const float* b2   = (const float*)d_in[11];
    const float* wf1  = (const float*)d_in[12];
    const float* bf1  = (const float*)d_in[13];
    const float* wf2  = (const float*)d_in[14];
    const float* bf2  = (const float*)d_in[15];
    float* out = (float*)d_out;

    float *p_h, *p_qkv, *p_att, *p_y2, *p_u, *p_wtqkv, *p_wtf1, *p_wtf2, *p_bqkv;
    cudaGetSymbolAddress((void**)&p_h,     g_h);
    cudaGetSymbolAddress((void**)&p_qkv,   g_qkv);
    cudaGetSymbolAddress((void**)&p_att,   g_att);
    cudaGetSymbolAddress((void**)&p_y2,    g_y2);
    cudaGetSymbolAddress((void**)&p_u,     g_u);
    cudaGetSymbolAddress((void**)&p_wtqkv, g_wt_qkv);
    cudaGetSymbolAddress((void**)&p_wtf1,  g_wt_f1);
    cudaGetSymbolAddress((void**)&p_wtf2,  g_wt_f2);
    cudaGetSymbolAddress((void**)&p_bqkv,  g_bqkv);

    cudaFuncSetAttribute(tgemm<false, false>, cudaFuncAttributeMaxDynamicSharedMemorySize, SMEM_BYTES);
    cudaFuncSetAttribute(tgemm<true,  false>, cudaFuncAttributeMaxDynamicSharedMemorySize, SMEM_BYTES);
    cudaFuncSetAttribute(tgemm<false, true >, cudaFuncAttributeMaxDynamicSharedMemorySize, SMEM_BYTES);

    dim3 t32(32, 8);
    // 0. pack transposed weights + fused qkv bias
    transpose_k<<<dim3(8, 8),  t32>>>(wq,  p_wtqkv,           256, 256);
    transpose_k<<<dim3(8, 8),  t32>>>(wk,  p_wtqkv + 65536,   256, 256);
    transpose_k<<<dim3(8, 8),  t32>>>(wv,  p_wtqkv + 131072,  256, 256);
    transpose_k<<<dim3(32, 8), t32>>>(wf1, p_wtf1,            256, 1024);
    transpose_k<<<dim3(8, 32), t32>>>(wf2, p_wtf2,            1024, 256);
    pack_bias_qkv<<<1, 256>>>(bq, bk, bv, p_bqkv);

    // 1. LN1 + shift + window partition (warp per row)
    ln1_window_kernel<<<MTOK / 8, 256>>>(x, g1, b1, p_h);

    // 2. fused QKV projection (tf32 tensor cores, cp.async pipeline)
    tgemm<false, false><<<dim3(768 / 128, MTOK / 128), 256, SMEM_BYTES>>>(
        p_h, p_wtqkv, p_bqkv, nullptr, p_qkv, MTOK, 768, CD);

    // 3. windowed attention (bias + mask + softmax fused)
    attn_kernel<<<NWIN * 8, 256>>>(p_qkv, tbl, p_att);

    // 4. reverse window/roll + residual + LN2 (warp per row)
    unwin_res_ln2<<<MTOK / 8, 256>>>(x, p_att, g2, b2, p_y2);

    // 5. MLP: fc1 + exact GELU, then fc2 + residual (writes final output)
    tgemm<true,  false><<<dim3(HIDDEN / 128, MTOK / 128), 256, SMEM_BYTES>>>(
        p_y2, p_wtf1, bf1, nullptr, p_u, MTOK, HIDDEN, CD);
    tgemm<false, true ><<<dim3(CD / 128, MTOK / 128), 256, SMEM_BYTES>>>(
        p_u, p_wtf2, bf2, p_y2, out, MTOK, CD, HIDDEN);
}

// round 12
// speedup vs baseline: 3.5792x; 1.2116x over previous
#include <cuda_runtime.h>
#include <cuda_bf16.h>
#include <math.h>
#include <stdint.h>

typedef __nv_bfloat16 bf16;

// Problem constants (B=2, H=W=256, C=256, NH=8, WS=8, SHIFT=4)
#define MTOK   131072
#define CD     256
#define NWIN   2048
#define HIDDEN 1024

// ---------------- static scratch ----------------
__device__ __align__(16) bf16  g_h   [(size_t)MTOK * CD];       // LN1 out (bf16 GEMM A)
__device__ float g_qkv [(size_t)MTOK * 768];                    // fused QKV out (fp32)
__device__ float g_att [(size_t)MTOK * CD];                     // attn out
__device__ float g_y2f [(size_t)MTOK * CD];                     // LN2 out fp32 (residual)
__device__ __align__(16) bf16  g_y2b [(size_t)MTOK * CD];       // LN2 out bf16 (GEMM A)
__device__ __align__(16) bf16  g_u   [(size_t)MTOK * HIDDEN];   // fc1+gelu out (bf16)
// pre-transposed bf16 weights [N][K]
__device__ __align__(16) bf16 g_wt_qkv[768 * 256];
__device__ __align__(16) bf16 g_wt_f1 [1024 * 256];
__device__ __align__(16) bf16 g_wt_f2 [256 * 1024];
__device__ float g_bqkv[768];

__device__ __forceinline__ uint32_t pkbf(float a, float b) {
    __nv_bfloat162 t = __floats2bfloat162_rn(a, b);
    return reinterpret_cast<uint32_t&>(t);
}

// ---------------- weight transpose: src fp32 [R][Cc] -> dst bf16 [Cc][R] ----------------
__global__ void transpose_bf(const float* __restrict__ src, bf16* __restrict__ dst,
                             int R, int Cc) {
    __shared__ float t[32][33];
    int bx = blockIdx.x * 32, by = blockIdx.y * 32;
    int x = bx + threadIdx.x;
#pragma unroll
    for (int i = 0; i < 32; i += 8) {
        int y = by + threadIdx.y + i;
        t[threadIdx.y + i][threadIdx.x] = src[(size_t)y * Cc + x];
    }
    __syncthreads();
    int x2 = by + threadIdx.x;
#pragma unroll
    for (int i = 0; i < 32; i += 8) {
        int y2 = bx + threadIdx.y + i;
        dst[(size_t)y2 * R + x2] = __float2bfloat16_rn(t[threadIdx.x][threadIdx.y + i]);
    }
}

__global__ void pack_bias_qkv(const float* __restrict__ bq, const float* __restrict__ bk,
                              const float* __restrict__ bv, float* __restrict__ bqkv) {
    int t = threadIdx.x;
    bqkv[t]       = bq[t];
    bqkv[256 + t] = bk[t];
    bqkv[512 + t] = bv[t];
}

// ---------------- warp-level dual reduction ----------------
__device__ __forceinline__ void warpReduce2(float& a, float& b) {
#pragma unroll
    for (int o = 16; o; o >>= 1) {
        a += __shfl_xor_sync(0xffffffffu, a, o);
        b += __shfl_xor_sync(0xffffffffu, b, o);
    }
}

// ---------------- kernel 1: LN1 + shift-roll + window partition (warp/row, bf16 out) -----
__global__ void ln1_window_kernel(const float* __restrict__ x,
                                  const float* __restrict__ g1,
                                  const float* __restrict__ b1,
                                  bf16* __restrict__ h) {
    int m = blockIdx.x * 8 + (threadIdx.x >> 5);
    int lane = threadIdx.x & 31;
    int bw = m >> 6, n = m & 63;
    int bb = bw >> 10, widx = bw & 1023;
    int wh = widx >> 5, ww = widx & 31;
    int r = n >> 3, c = n & 7;
    int gh = (wh * 8 + r + 4) & 255;
    int gw = (ww * 8 + c + 4) & 255;
    const float* row = x + ((size_t)bb * 65536 + (size_t)gh * 256 + gw) * CD;
    int ch = lane * 8;
    float4 v0 = *(const float4*)(row + ch);
    float4 v1 = *(const float4*)(row + ch + 4);
    float a = v0.x + v0.y + v0.z + v0.w + v1.x + v1.y + v1.z + v1.w;
    float b = v0.x * v0.x + v0.y * v0.y + v0.z * v0.z + v0.w * v0.w
            + v1.x * v1.x + v1.y * v1.y + v1.z * v1.z + v1.w * v1.w;
    warpReduce2(a, b);
    float mu = a * (1.0f / CD);
    float rstd = rsqrtf(b * (1.0f / CD) - mu * mu + 1e-5f);
    float4 ga = *(const float4*)(g1 + ch);
    float4 gb = *(const float4*)(g1 + ch + 4);
    float4 ba = *(const float4*)(b1 + ch);
    float4 bbv = *(const float4*)(b1 + ch + 4);
    uint4 st;
    st.x = pkbf((v0.x - mu) * rstd * ga.x + ba.x,  (v0.y - mu) * rstd * ga.y + ba.y);
    st.y = pkbf((v0.z - mu) * rstd * ga.z + ba.z,  (v0.w - mu) * rstd * ga.w + ba.w);
    st.z = pkbf((v1.x - mu) * rstd * gb.x + bbv.x, (v1.y - mu) * rstd * gb.y + bbv.y);
    st.w = pkbf((v1.z - mu) * rstd * gb.z + bbv.z, (v1.w - mu) * rstd * gb.w + bbv.w);
    *(uint4*)(h + (size_t)m * CD + ch) = st;
}

// ---------------- bf16 tensor-core GEMM, cp.async 3-stage, BK=64, 2 CTAs/SM -------------
__device__ __forceinline__ void ldsm4(uint32_t& r0, uint32_t& r1, uint32_t& r2, uint32_t& r3,
                                      uint32_t addr) {
    asm volatile("ldmatrix.sync.aligned.m8n8.x4.shared.b16 {%0,%1,%2,%3}, [%4];"
                 : "=r"(r0), "=r"(r1), "=r"(r2), "=r"(r3) : "r"(addr));
}
__device__ __forceinline__ void mma_bf16(float* c, const uint32_t* a, const uint32_t* b) {
    asm volatile(
        "mma.sync.aligned.m16n8k16.row.col.f32.bf16.bf16.f32 "
        "{%0,%1,%2,%3}, {%4,%5,%6,%7}, {%8,%9}, {%0,%1,%2,%3};"
        : "+f"(c[0]), "+f"(c[1]), "+f"(c[2]), "+f"(c[3])
        : "r"(a[0]), "r"(a[1]), "r"(a[2]), "r"(a[3]), "r"(b[0]), "r"(b[1]));
}
#define CP_COMMIT() asm volatile("cp.async.commit_group;")

#define ROWB 144                       // 128B data + 16B pad: 144 % 128 = 16 -> LDSM conflict-free
#define OPBYTES (128 * ROWB)           // 18432
#define STG_BYTES (2 * OPBYTES)        // 36864
#define STAGES 3
#define SMEM_BYTES (STAGES * STG_BYTES)

// one stage fill (BK=64 bf16 = 128B/row): 4 x 16B cp.async per thread per operand
__device__ __forceinline__ void fill_stage(uint32_t sA, uint32_t sB,
                                           const bf16* __restrict__ A,
                                           const bf16* __restrict__ Bt,
                                           int m0, int n0, int K, int k0, int tid) {
#pragma unroll
    for (int i = 0; i < 4; i++) {
        int idx = tid + 256 * i;
        int rm = idx >> 3, g = idx & 7;
        uint32_t doff = (uint32_t)(rm * ROWB + g * 16);
        const bf16* ga = A + (size_t)(m0 + rm) * K + k0 + g * 8;
        asm volatile("cp.async.cg.shared.global [%0], [%1], 16;" :: "r"(sA + doff), "l"(ga));
        const bf16* gb = Bt + (size_t)(n0 + rm) * K + k0 + g * 8;
        asm volatile("cp.async.cg.shared.global [%0], [%1], 16;" :: "r"(sB + doff), "l"(gb));
    }
}

// C[M,Nn] = A[M,K] @ Bt[Nn,K]^T + bias (+GELU / +res). BM=BN=128, BK=64.
// 8 warps (4m x 2n), warp tile 32x64; m16n8k16 frags.
template <bool GELU, bool RES, bool OUTBF>
__global__ void __launch_bounds__(256, 2)
tgemm(const bf16* __restrict__ A, const bf16* __restrict__ Bt,
      const float* __restrict__ bias, const float* __restrict__ res,
      void* __restrict__ Cout, int M, int Nn, int K) {
    extern __shared__ __align__(16) char smem[];
    int tid = threadIdx.x;
    int lane = tid & 31, wid = tid >> 5;
    int wm = wid >> 1, wn = wid & 1;
    int m0 = blockIdx.y * 128, n0 = blockIdx.x * 128;
    uint32_t base = (uint32_t)__cvta_generic_to_shared(smem);

    float acc[2][8][4] = {};
    const int NITER = K >> 6;

#pragma unroll
    for (int s = 0; s < STAGES - 1; s++) {
        if (s < NITER) {
            uint32_t sA = base + s * STG_BYTES;
            fill_stage(sA, sA + OPBYTES, A, Bt, m0, n0, K, s * 64, tid);
        }
        CP_COMMIT();
    }

    int l7 = lane & 7, lh = (lane >> 3) & 1, ls = lane >> 4;
    for (int it = 0; it < NITER; it++) {
        asm volatile("cp.async.wait_group %0;" :: "n"(STAGES - 2));
        __syncthreads();

        int nxt = it + STAGES - 1;
        if (nxt < NITER) {
            uint32_t sA = base + (nxt % STAGES) * STG_BYTES;
            fill_stage(sA, sA + OPBYTES, A, Bt, m0, n0, K, nxt * 64, tid);
        }
        CP_COMMIT();

        uint32_t sA = base + (it % STAGES) * STG_BYTES;
        uint32_t sB = sA + OPBYTES;
#pragma unroll
        for (int kk = 0; kk < 4; kk++) {           // 4 x k16 per BK=64
            uint32_t af[2][4];
#pragma unroll
            for (int mt = 0; mt < 2; mt++) {
                int row = wm * 32 + mt * 16 + l7 + lh * 8;
                ldsm4(af[mt][0], af[mt][1], af[mt][2], af[mt][3],
                      sA + (uint32_t)(row * ROWB + kk * 32 + ls * 16));
            }
            uint32_t bfr[4][4];
#pragma unroll
            for (int p = 0; p < 4; p++) {
                int row = wn * 64 + p * 16 + l7 + ls * 8;
                ldsm4(bfr[p][0], bfr[p][1], bfr[p][2], bfr[p][3],
                      sB + (uint32_t)(row * ROWB + kk * 32 + lh * 16));
            }
#pragma unroll
            for (int mt = 0; mt < 2; mt++)
#pragma unroll
                for (int p = 0; p < 4; p++) {
                    mma_bf16(acc[mt][2 * p],     af[mt], &bfr[p][0]);
                    mma_bf16(acc[mt][2 * p + 1], af[mt], &bfr[p][2]);
                }
        }
        __syncthreads();
    }

    // epilogue: C frag: d0 (r,c), d1 (r,c+1), d2 (r+8,c), d3 (r+8,c+1)
    int r0 = lane >> 2, c0 = (lane & 3) << 1;
#pragma unroll
    for (int mt = 0; mt < 2; mt++) {
#pragma unroll
        for (int half = 0; half < 2; half++) {
            int row = m0 + wm * 32 + mt * 16 + half * 8 + r0;
#pragma unroll
            for (int nt = 0; nt < 8; nt++) {
                int col = n0 + wn * 64 + ((nt >> 1) << 4) + ((nt & 1) << 3) + c0;
                float v0 = acc[mt][nt][half * 2 + 0] + bias[col];
                float v1 = acc[mt][nt][half * 2 + 1] + bias[col + 1];
                if (GELU) {
                    v0 = 0.5f * v0 * (1.0f + erff(v0 * 0.70710678118654752f));
                    v1 = 0.5f * v1 * (1.0f + erff(v1 * 0.70710678118654752f));
                }
                if (RES) {
                    v0 += res[(size_t)row * Nn + col];
                    v1 += res[(size_t)row * Nn + col + 1];
                }
                if (OUTBF) {
                    *(uint32_t*)((bf16*)Cout + (size_t)row * Nn + col) = pkbf(v0, v1);
                } else {
                    *(float2*)((float*)Cout + (size_t)row * Nn + col) = make_float2(v0, v1);
                }
            }
        }
    }
}

// ---------------- kernel 3: windowed attention (fp32, unchanged) ----------------
__global__ void attn_kernel(const float* __restrict__ qkv,
                            const float* __restrict__ bias_table,
                            float* __restrict__ attn_out) {
    int blk = blockIdx.x;               // bw*8 + head
    int bw = blk >> 3, head = blk & 7;
    int widx = bw & 1023;
    int wh = widx >> 5, ww = widx & 31;
    int tid = threadIdx.x;

    __shared__ float sq[64][33];
    __shared__ float sk[64][33];
    __shared__ float sv[64][36];
    __shared__ float sc[64][65];
    __shared__ int   lab[64];

    {
        int n = tid >> 2, d0 = (tid & 3) << 3;
        size_t off = ((size_t)bw * 64 + n) * 768 + head * 32 + d0;
        float4 a0 = *(const float4*)(qkv + off);
        float4 a1 = *(const float4*)(qkv + off + 4);
        sq[n][d0 + 0] = a0.x; sq[n][d0 + 1] = a0.y; sq[n][d0 + 2] = a0.z; sq[n][d0 + 3] = a0.w;
        sq[n][d0 + 4] = a1.x; sq[n][d0 + 5] = a1.y; sq[n][d0 + 6] = a1.z; sq[n][d0 + 7] = a1.w;
        float4 c0 = *(const float4*)(qkv + off + 256);
        float4 c1 = *(const float4*)(qkv + off + 260);
        sk[n][d0 + 0] = c0.x; sk[n][d0 + 1] = c0.y; sk[n][d0 + 2] = c0.z; sk[n][d0 + 3] = c0.w;
        sk[n][d0 + 4] = c1.x; sk[n][d0 + 5] = c1.y; sk[n][d0 + 6] = c1.z; sk[n][d0 + 7] = c1.w;
        float4 v0 = *(const float4*)(qkv + off + 512);
        float4 v1 = *(const float4*)(qkv + off + 516);
        *(float4*)&sv[n][d0]     = v0;
        *(float4*)&sv[n][d0 + 4] = v1;
    }
    if (tid < 64) {
        int ri = tid >> 3, ci = tid & 7;
        int srow = wh * 8 + ri, scol = ww * 8 + ci;
        int lh2 = (srow < 248) ? 0 : ((srow < 252) ? 1 : 2);
        int lw2 = (scol < 248) ? 0 : ((scol < 252) ? 1 : 2);
        lab[tid] = lh2 * 3 + lw2;
    }
    __syncthreads();

    {
        int i0 = (tid >> 4) << 2, j0 = (tid & 15) << 2;
        float accs[4][4] = {};
#pragma unroll 8
        for (int d = 0; d < 32; d++) {
            float a0 = sq[i0 + 0][d], a1 = sq[i0 + 1][d], a2 = sq[i0 + 2][d], a3 = sq[i0 + 3][d];
            float b0 = sk[j0 + 0][d], b1 = sk[j0 + 1][d], b2 = sk[j0 + 2][d], b3 = sk[j0 + 3][d];
            accs[0][0] += a0 * b0; accs[0][1] += a0 * b1; accs[0][2] += a0 * b2; accs[0][3] += a0 * b3;
            accs[1][0] += a1 * b0; accs[1][1] += a1 * b1; accs[1][2] += a1 * b2; accs[1][3] += a1 * b3;
            accs[2][0] += a2 * b0; accs[2][1] += a2 * b1; accs[2][2] += a2 * b2; accs[2][3] += a2 * b3;
            accs[3][0] += a3 * b0; accs[3][1] += a3 * b1; accs[3][2] += a3 * b2; accs[3][3] += a3 * b3;
        }
        const float sscale = 0.17677669529663687f;
#pragma unroll
        for (int ii = 0; ii < 4; ii++) {
            int i = i0 + ii;
            int ri = i >> 3, ci = i & 7, li = lab[i];
#pragma unroll
            for (int jj = 0; jj < 4; jj++) {
                int j = j0 + jj;
                int rj = j >> 3, cj = j & 7;
                int rel = (ri - rj + 7) * 15 + (ci - cj + 7);
                float s = accs[ii][jj] * sscale + bias_table[rel * 8 + head];
                if (li != lab[j]) s -= 100.0f;
                sc[i][j] = s;
            }
        }
    }
    __syncthreads();

    {
        int row = tid >> 2, sub = tid & 3;
        float mx = -1e30f;
#pragma unroll
        for (int t = 0; t < 16; t++) mx = fmaxf(mx, sc[row][sub * 16 + t]);
        mx = fmaxf(mx, __shfl_xor_sync(0xffffffffu, mx, 1));
        mx = fmaxf(mx, __shfl_xor_sync(0xffffffffu, mx, 2));
        float sum = 0.f;
#pragma unroll
        for (int t = 0; t < 16; t++) {
            float e = __expf(sc[row][sub * 16 + t] - mx);
            sc[row][sub * 16 + t] = e;
            sum += e;
        }
        sum += __shfl_xor_sync(0xffffffffu, sum, 1);
        sum += __shfl_xor_sync(0xffffffffu, sum, 2);
        float inv = 1.0f / sum;
#pragma unroll
        for (int t = 0; t < 16; t++) sc[row][sub * 16 + t] *= inv;
    }
    __syncthreads();

    {
        int i = tid >> 2, d0 = (tid & 3) << 3;
        float acc[8] = {};
#pragma unroll 16
        for (int j = 0; j < 64; j++) {
            float s = sc[i][j];
            float4 v0 = *(const float4*)&sv[j][d0];
            float4 v1 = *(const float4*)&sv[j][d0 + 4];
            acc[0] += s * v0.x; acc[1] += s * v0.y; acc[2] += s * v0.z; acc[3] += s * v0.w;
            acc[4] += s * v1.x; acc[5] += s * v1.y; acc[6] += s * v1.z; acc[7] += s * v1.w;
        }
        size_t o = (((size_t)bw * 8 + head) * 64 + i) * 32 + d0;
        float4 o0 = {acc[0], acc[1], acc[2], acc[3]};
        float4 o1 = {acc[4], acc[5], acc[6], acc[7]};
        *(float4*)&attn_out[o]     = o0;
        *(float4*)&attn_out[o + 4] = o1;
    }
}

// ---------------- kernel 4: un-window + un-roll + residual + LN2 (warp/row) -------------
// writes fp32 (residual) + bf16 (GEMM A) copies
__global__ void unwin_res_ln2(const float* __restrict__ x, const float* __restrict__ att,
                              const float* __restrict__ g2, const float* __restrict__ b2,
                              float* __restrict__ y2f, bf16* __restrict__ y2b) {
    int m = blockIdx.x * 8 + (threadIdx.x >> 5);
    int lane = threadIdx.x & 31;
    int bb = m >> 16, l = m & 65535;
    int gh = l >> 8, gw = l & 255;
    int sh = (gh + 252) & 255, sw = (gw + 252) & 255;
    int wh = sh >> 3, r = sh & 7, ww = sw >> 3, c = sw & 7;
    size_t base = ((size_t)((bb * 1024 + wh * 32 + ww) * 8 + r) * 64 + (size_t)c * 8) * 32;
    int ch = lane * 8;
    const float* xr = x + (size_t)m * CD + ch;
    const float* ar = att + base + ch;
    float4 x0 = *(const float4*)xr;
    float4 x1 = *(const float4*)(xr + 4);
    float4 a0 = *(const float4*)ar;
    float4 a1 = *(const float4*)(ar + 4);
    float4 v0 = {x0.x + a0.x, x0.y + a0.y, x0.z + a0.z, x0.w + a0.w};
    float4 v1 = {x1.x + a1.x, x1.y + a1.y, x1.z + a1.z, x1.w + a1.w};
    float a = v0.x + v0.y + v0.z + v0.w + v1.x + v1.y + v1.z + v1.w;
    float b = v0.x * v0.x + v0.y * v0.y + v0.z * v0.z + v0.w * v0.w
            + v1.x * v1.x + v1.y * v1.y + v1.z * v1.z + v1.w * v1.w;
    warpReduce2(a, b);
    float mu = a * (1.0f / CD);
    float rstd = rsqrtf(b * (1.0f / CD) - mu * mu + 1e-5f);
    float4 ga = *(const float4*)(g2 + ch);
    float4 gb = *(const float4*)(g2 + ch + 4);
    float4 ba = *(const float4*)(b2 + ch);
    float4 bbv = *(const float4*)(b2 + ch + 4);
    float4 o0, o1;
    o0.x = (v0.x - mu) * rstd * ga.x + ba.x;
    o0.y = (v0.y - mu) * rstd * ga.y + ba.y;
    o0.z = (v0.z - mu) * rstd * ga.z + ba.z;
    o0.w = (v0.w - mu) * rstd * ga.w + ba.w;
    o1.x = (v1.x - mu) * rstd * gb.x + bbv.x;
    o1.y = (v1.y - mu) * rstd * gb.y + bbv.y;
    o1.z = (v1.z - mu) * rstd * gb.z + bbv.z;
    o1.w = (v1.w - mu) * rstd * gb.w + bbv.w;
    float* dstf = y2f + (size_t)m * CD + ch;
    *(float4*)dstf = o0;
    *(float4*)(dstf + 4) = o1;
    uint4 st = { pkbf(o0.x, o0.y), pkbf(o0.z, o0.w), pkbf(o1.x, o1.y), pkbf(o1.z, o1.w) };
    *(uint4*)(y2b + (size_t)m * CD + ch) = st;
}

// ---------------- host launch ----------------
extern "C" void kernel_launch(void* const* d_in, const int* in_sizes, int n_in,
                              void* d_out, int out_size) {
    (void)in_sizes; (void)n_in; (void)out_size;
    const float* x    = (const float*)d_in[0];
    const float* g1   = (const float*)d_in[1];
    const float* b1   = (const float*)d_in[2];
    const float* wq   = (const float*)d_in[3];
    const float* bq   = (const float*)d_in[4];
    const float* wk   = (const float*)d_in[5];
    const float* bk   = (const float*)d_in[6];
    const float* wv   = (const float*)d_in[7];
    const float* bv   = (const float*)d_in[8];
    const float* tbl  = (const float*)d_in[9];
    const float* g2   = (const float*)d_in[10];
    const float* b2   = (const float*)d_in[11];
    const float* wf1  = (const float*)d_in[12];
    const float* bf1  = (const float*)d_in[13];
    const float* wf2  = (const float*)d_in[14];
    const float* bf2  = (const float*)d_in[15];
    float* out = (float*)d_out;

    bf16 *p_h, *p_y2b, *p_u, *p_wtqkv, *p_wtf1, *p_wtf2;
    float *p_qkv, *p_att, *p_y2f, *p_bqkv;
    cudaGetSymbolAddress((void**)&p_h,     g_h);
    cudaGetSymbolAddress((void**)&p_qkv,   g_qkv);
    cudaGetSymbolAddress((void**)&p_att,   g_att);
    cudaGetSymbolAddress((void**)&p_y2f,   g_y2f);
    cudaGetSymbolAddress((void**)&p_y2b,   g_y2b);
    cudaGetSymbolAddress((void**)&p_u,     g_u);
    cudaGetSymbolAddress((void**)&p_wtqkv, g_wt_qkv);
    cudaGetSymbolAddress((void**)&p_wtf1,  g_wt_f1);
    cudaGetSymbolAddress((void**)&p_wtf2,  g_wt_f2);
    cudaGetSymbolAddress((void**)&p_bqkv,  g_bqkv);

    cudaFuncSetAttribute(tgemm<false, false, false>, cudaFuncAttributeMaxDynamicSharedMemorySize, SMEM_BYTES);
    cudaFuncSetAttribute(tgemm<true,  false, true >, cudaFuncAttributeMaxDynamicSharedMemorySize, SMEM_BYTES);
    cudaFuncSetAttribute(tgemm<false, true,  false>, cudaFuncAttributeMaxDynamicSharedMemorySize, SMEM_BYTES);

    dim3 t32(32, 8);
    // 0. pack transposed bf16 weights + fused qkv bias
    transpose_bf<<<dim3(8, 8),  t32>>>(wq,  p_wtqkv,           256, 256);
    transpose_bf<<<dim3(8, 8),  t32>>>(wk,  p_wtqkv + 65536,   256, 256);
    transpose_bf<<<dim3(8, 8),  t32>>>(wv,  p_wtqkv + 131072,  256, 256);
    transpose_bf<<<dim3(32, 8), t32>>>(wf1, p_wtf1,            256, 1024);
    transpose_bf<<<dim3(8, 32), t32>>>(wf2, p_wtf2,            1024, 256);
    pack_bias_qkv<<<1, 256>>>(bq, bk, bv, p_bqkv);

    // 1. LN1 + shift + window partition (warp per row, bf16 out)
    ln1_window_kernel<<<MTOK / 8, 256>>>(x, g1, b1, p_h);

    // 2. fused QKV projection (bf16 mma, fp32 out)
    tgemm<false, false, false><<<dim3(768 / 128, MTOK / 128), 256, SMEM_BYTES>>>(
        p_h, p_wtqkv, p_bqkv, nullptr, p_qkv, MTOK, 768, CD);

    // 3. windowed attention (bias + mask + softmax fused)
    attn_kernel<<<NWIN * 8, 256>>>(p_qkv, tbl, p_att);

    // 4. reverse window/roll + residual + LN2 (fp32 + bf16 outputs)
    unwin_res_ln2<<<MTOK / 8, 256>>>(x, p_att, g2, b2, p_y2f, p_y2b);

    // 5. MLP: fc1 + exact GELU (bf16 out), then fc2 + residual (fp32 final)
    tgemm<true, false, true><<<dim3(HIDDEN / 128, MTOK / 128), 256, SMEM_BYTES>>>(
        p_y2b, p_wtf1, bf1, nullptr, p_u, MTOK, HIDDEN, CD);
    tgemm<false, true, false><<<dim3(CD / 128, MTOK / 128), 256, SMEM_BYTES>>>(
        p_u, p_wtf2, bf2, p_y2f, out, MTOK, CD, HIDDEN);
}